// round 1
// baseline (speedup 1.0000x reference)
#include <cuda_runtime.h>
#include <math.h>

// Problem constants
#define Bq   4
#define Nq   2048
#define Cq   1024
#define Hq   16
#define Dq   64
#define Rq   16
#define Mq   (Bq*Nq)          // 8192 rows
#define C3q  (3*Cq)           // 3072
#define SCALEF 0.125f         // 1/sqrt(64)

// Scratch (device globals — no cudaMalloc allowed)
__device__ float g_P [Mq*Rq];        // lora intermediate [M,R]
__device__ float g_q [Mq*Cq];        // [B,H,N,D]
__device__ float g_k [Mq*Cq];        // [B,H,N,D]
__device__ float g_v [Mq*Cq];        // [B,H,N,D]
__device__ float g_ao[Mq*Cq];        // attention out, [B,N,C]

// ---------------------------------------------------------------------------
// Kernel 1: P = query @ W_loraA   ([8192,1024] @ [1024,16])
// One block per row, 256 threads, warp-shuffle reduction.
// ---------------------------------------------------------------------------
__global__ void lora_p_kernel(const float* __restrict__ query,
                              const float* __restrict__ WA) {
    const int row  = blockIdx.x;
    const int tid  = threadIdx.x;
    const int lane = tid & 31;
    const int wid  = tid >> 5;

    float acc[Rq];
#pragma unroll
    for (int r = 0; r < Rq; r++) acc[r] = 0.f;

    const float* qr = query + (size_t)row * Cq;
    for (int c = tid; c < Cq; c += 256) {
        float qv = qr[c];
        const float4* wa = (const float4*)(WA + (size_t)c * Rq);
        float4 w0 = wa[0], w1 = wa[1], w2 = wa[2], w3 = wa[3];
        acc[0]  += qv * w0.x; acc[1]  += qv * w0.y; acc[2]  += qv * w0.z; acc[3]  += qv * w0.w;
        acc[4]  += qv * w1.x; acc[5]  += qv * w1.y; acc[6]  += qv * w1.z; acc[7]  += qv * w1.w;
        acc[8]  += qv * w2.x; acc[9]  += qv * w2.y; acc[10] += qv * w2.z; acc[11] += qv * w2.w;
        acc[12] += qv * w3.x; acc[13] += qv * w3.y; acc[14] += qv * w3.z; acc[15] += qv * w3.w;
    }
#pragma unroll
    for (int r = 0; r < Rq; r++) {
#pragma unroll
        for (int off = 16; off > 0; off >>= 1)
            acc[r] += __shfl_down_sync(0xffffffffu, acc[r], off);
    }
    __shared__ float part[8][Rq];
    if (lane == 0) {
#pragma unroll
        for (int r = 0; r < Rq; r++) part[wid][r] = acc[r];
    }
    __syncthreads();
    if (tid < Rq) {
        float s = 0.f;
#pragma unroll
        for (int w = 0; w < 8; w++) s += part[w][tid];
        g_P[(size_t)row * Rq + tid] = s;
    }
}

// ---------------------------------------------------------------------------
// Kernel 2: qkv = query @ W_qkv, scatter to [B,H,N,D] q/k/v buffers.
// q gets DoRA delta: + magnitude[h] * (P @ W_loraB) fused in epilogue.
// 64x64 tile, 256 threads (16x16), 4x4 per thread, BK=16.
// ---------------------------------------------------------------------------
__global__ void qkv_gemm_kernel(const float* __restrict__ A,
                                const float* __restrict__ W,
                                const float* __restrict__ mag,
                                const float* __restrict__ WB) {
    __shared__ float As[16][68];   // [k][m]
    __shared__ float Bs[16][68];   // [k][n]
    __shared__ float WBs[16][64];  // lora B slice for q blocks

    const int bn = blockIdx.x * 64;
    const int bm = blockIdx.y * 64;
    const int t  = threadIdx.x;
    const int tx = t & 15, ty = t >> 4;
    const bool is_q = (bn < Cq);

    if (is_q) {
        int r = t >> 4, n4 = (t & 15) * 4;
        *(float4*)&WBs[r][n4] = *(const float4*)(WB + (size_t)r * Cq + bn + n4);
    }

    float acc[4][4] = {};
    for (int k0 = 0; k0 < Cq; k0 += 16) {
        {
            int lm = t >> 2, lk = (t & 3) * 4;
            float4 a4 = *(const float4*)(A + (size_t)(bm + lm) * Cq + k0 + lk);
            As[lk + 0][lm] = a4.x; As[lk + 1][lm] = a4.y;
            As[lk + 2][lm] = a4.z; As[lk + 3][lm] = a4.w;
            int bk = t >> 4, ln = (t & 15) * 4;
            *(float4*)&Bs[bk][ln] =
                *(const float4*)(W + (size_t)(k0 + bk) * C3q + bn + ln);
        }
        __syncthreads();
#pragma unroll
        for (int k = 0; k < 16; k++) {
            float ar[4], br[4];
#pragma unroll
            for (int i = 0; i < 4; i++) ar[i] = As[k][ty * 4 + i];
#pragma unroll
            for (int j = 0; j < 4; j++) br[j] = Bs[k][tx * 4 + j];
#pragma unroll
            for (int i = 0; i < 4; i++)
#pragma unroll
                for (int j = 0; j < 4; j++) acc[i][j] += ar[i] * br[j];
        }
        __syncthreads();
    }

    // Epilogue: scatter into q/k/v [B,H,N,D]; add DoRA delta to q.
#pragma unroll
    for (int i = 0; i < 4; i++) {
        int row = bm + ty * 4 + i;
        int b = row >> 11, n = row & (Nq - 1);
        float pr[Rq];
        if (is_q) {
            const float* pp = g_P + (size_t)row * Rq;
#pragma unroll
            for (int r = 0; r < Rq; r++) pr[r] = pp[r];
        }
#pragma unroll
        for (int j = 0; j < 4; j++) {
            int col    = bn + tx * 4 + j;
            int within = col & (Cq - 1);
            int h = within >> 6, d = within & 63;
            size_t oidx = ((((size_t)b * Hq + h) * Nq) + n) * Dq + d;
            float v = acc[i][j];
            if (col < Cq) {
                float del = 0.f;
#pragma unroll
                for (int r = 0; r < Rq; r++) del += pr[r] * WBs[r][tx * 4 + j];
                v += mag[h] * del;
                g_q[oidx] = v;
            } else if (col < 2 * Cq) {
                g_k[oidx] = v;
            } else {
                g_v[oidx] = v;
            }
        }
    }
}

// ---------------------------------------------------------------------------
// Kernel 3: flash attention (fp32, online softmax).
// Block = (b,h,qtile of 64 rows). 256 threads, 4x4 register tiles.
// K tile stored transposed ([d][c]) for conflict-free S compute.
// ---------------------------------------------------------------------------
#define PADA 68
__global__ void attn_kernel(const float* __restrict__ mask) {
    extern __shared__ float sm[];
    float* Qs = sm;                    // [64][PADA]  (Qs[r][d])
    float* Ks = Qs + 64 * PADA;        // [64][PADA]  (Ks[d][c]) transposed
    float* Vs = Ks + 64 * PADA;        // [64][PADA]  (Vs[c][d])
    float* Ps = Vs + 64 * PADA;        // [64][PADA]  scores / probs
    float* mrow = Ps + 64 * PADA;      // [64]
    float* lrow = mrow + 64;           // [64]
    float* rsrow = lrow + 64;          // [64]

    const int qt = blockIdx.x, h = blockIdx.y, b = blockIdx.z;
    const int t  = threadIdx.x;
    const int tx = t & 15, ty = t >> 4;

    const size_t base = ((size_t)b * Hq + h) * Nq;
    const float* Qg = g_q + (base + (size_t)qt * 64) * Dq;

    // Load Q tile (64x64) once
#pragma unroll
    for (int it = 0; it < 4; it++) {
        int idx = t + it * 256;
        int r = idx >> 4, d4 = (idx & 15) * 4;
        *(float4*)&Qs[r * PADA + d4] = *(const float4*)(Qg + r * Dq + d4);
    }
    if (t < 64) { mrow[t] = -1e30f; lrow[t] = 0.f; }

    float o[4][4] = {};
    const float* maskb = mask + (size_t)b * Nq * Nq + (size_t)(qt * 64) * Nq;

    for (int kt = 0; kt < Nq / 64; kt++) {
        __syncthreads();  // protect Ks/Vs from previous iteration's readers
        const float* Kg = g_k + (base + (size_t)kt * 64) * Dq;
        const float* Vg = g_v + (base + (size_t)kt * 64) * Dq;
#pragma unroll
        for (int it = 0; it < 4; it++) {
            int idx = t + it * 256;
            int c = idx >> 4, d4 = (idx & 15) * 4;
            float4 kv = *(const float4*)(Kg + c * Dq + d4);
            Ks[(d4 + 0) * PADA + c] = kv.x;
            Ks[(d4 + 1) * PADA + c] = kv.y;
            Ks[(d4 + 2) * PADA + c] = kv.z;
            Ks[(d4 + 3) * PADA + c] = kv.w;
            *(float4*)&Vs[c * PADA + d4] = *(const float4*)(Vg + c * Dq + d4);
        }
        __syncthreads();

        // S = Q Kt
        float s[4][4] = {};
#pragma unroll
        for (int k = 0; k < 64; k++) {
            float ar[4], br[4];
#pragma unroll
            for (int i = 0; i < 4; i++) ar[i] = Qs[(ty * 4 + i) * PADA + k];
#pragma unroll
            for (int j = 0; j < 4; j++) br[j] = Ks[k * PADA + tx * 4 + j];
#pragma unroll
            for (int i = 0; i < 4; i++)
#pragma unroll
                for (int j = 0; j < 4; j++) s[i][j] += ar[i] * br[j];
        }
        // scale + mask, write to Ps
#pragma unroll
        for (int i = 0; i < 4; i++) {
            const float* mg = maskb + (size_t)(ty * 4 + i) * Nq + kt * 64 + tx * 4;
            float4 m4 = *(const float4*)mg;
            float4 sv;
            sv.x = s[i][0] * SCALEF + m4.x;
            sv.y = s[i][1] * SCALEF + m4.y;
            sv.z = s[i][2] * SCALEF + m4.z;
            sv.w = s[i][3] * SCALEF + m4.w;
            *(float4*)&Ps[(ty * 4 + i) * PADA + tx * 4] = sv;
        }
        __syncthreads();

        // Online softmax, one thread per row
        if (t < 64) {
            float* pr = Ps + t * PADA;
            float mx = mrow[t];
#pragma unroll
            for (int j = 0; j < 64; j++) mx = fmaxf(mx, pr[j]);
            float sc = __expf(mrow[t] - mx);
            float sum = 0.f;
#pragma unroll
            for (int j = 0; j < 64; j++) {
                float p = __expf(pr[j] - mx);
                pr[j] = p;
                sum += p;
            }
            lrow[t] = lrow[t] * sc + sum;
            mrow[t] = mx;
            rsrow[t] = sc;
        }
        __syncthreads();

        // O = O*rescale + P @ V
        float rs[4];
#pragma unroll
        for (int i = 0; i < 4; i++) rs[i] = rsrow[ty * 4 + i];
#pragma unroll
        for (int i = 0; i < 4; i++)
#pragma unroll
            for (int j = 0; j < 4; j++) o[i][j] *= rs[i];
#pragma unroll
        for (int jj = 0; jj < 64; jj++) {
            float pv[4], vv[4];
#pragma unroll
            for (int i = 0; i < 4; i++) pv[i] = Ps[(ty * 4 + i) * PADA + jj];
#pragma unroll
            for (int j = 0; j < 4; j++) vv[j] = Vs[jj * PADA + tx * 4 + j];
#pragma unroll
            for (int i = 0; i < 4; i++)
#pragma unroll
                for (int j = 0; j < 4; j++) o[i][j] += pv[i] * vv[j];
        }
    }

    // Epilogue: normalize, write to [B,N,C] buffer
#pragma unroll
    for (int i = 0; i < 4; i++) {
        int r = ty * 4 + i;
        float inv = 1.0f / lrow[r];
        int n = qt * 64 + r;
        float* op = g_ao + ((size_t)(b * Nq + n)) * Cq + h * Dq + tx * 4;
        float4 ov;
        ov.x = o[i][0] * inv; ov.y = o[i][1] * inv;
        ov.z = o[i][2] * inv; ov.w = o[i][3] * inv;
        *(float4*)op = ov;
    }
}

// ---------------------------------------------------------------------------
// Kernel 4: out = g_ao @ W_proj  ([8192,1024] @ [1024,1024])
// ---------------------------------------------------------------------------
__global__ void proj_gemm_kernel(const float* __restrict__ W,
                                 float* __restrict__ out) {
    __shared__ float As[16][68];
    __shared__ float Bs[16][68];

    const int bn = blockIdx.x * 64;
    const int bm = blockIdx.y * 64;
    const int t  = threadIdx.x;
    const int tx = t & 15, ty = t >> 4;

    float acc[4][4] = {};
    for (int k0 = 0; k0 < Cq; k0 += 16) {
        {
            int lm = t >> 2, lk = (t & 3) * 4;
            float4 a4 = *(const float4*)(g_ao + (size_t)(bm + lm) * Cq + k0 + lk);
            As[lk + 0][lm] = a4.x; As[lk + 1][lm] = a4.y;
            As[lk + 2][lm] = a4.z; As[lk + 3][lm] = a4.w;
            int bk = t >> 4, ln = (t & 15) * 4;
            *(float4*)&Bs[bk][ln] =
                *(const float4*)(W + (size_t)(k0 + bk) * Cq + bn + ln);
        }
        __syncthreads();
#pragma unroll
        for (int k = 0; k < 16; k++) {
            float ar[4], br[4];
#pragma unroll
            for (int i = 0; i < 4; i++) ar[i] = As[k][ty * 4 + i];
#pragma unroll
            for (int j = 0; j < 4; j++) br[j] = Bs[k][tx * 4 + j];
#pragma unroll
            for (int i = 0; i < 4; i++)
#pragma unroll
                for (int j = 0; j < 4; j++) acc[i][j] += ar[i] * br[j];
        }
        __syncthreads();
    }
#pragma unroll
    for (int i = 0; i < 4; i++) {
        int row = bm + ty * 4 + i;
        float4 ov;
        ov.x = acc[i][0]; ov.y = acc[i][1]; ov.z = acc[i][2]; ov.w = acc[i][3];
        *(float4*)(out + (size_t)row * Cq + bn + tx * 4) = ov;
    }
}

// ---------------------------------------------------------------------------
extern "C" void kernel_launch(void* const* d_in, const int* in_sizes, int n_in,
                              void* d_out, int out_size) {
    const float* query     = (const float*)d_in[0];
    const float* mask      = (const float*)d_in[1];
    const float* W_qkv     = (const float*)d_in[2];
    const float* magnitude = (const float*)d_in[3];
    const float* W_loraA   = (const float*)d_in[4];
    const float* W_loraB   = (const float*)d_in[5];
    const float* W_proj    = (const float*)d_in[6];
    float* out = (float*)d_out;

    lora_p_kernel<<<Mq, 256>>>(query, W_loraA);
    qkv_gemm_kernel<<<dim3(C3q / 64, Mq / 64), 256>>>(query, W_qkv, magnitude, W_loraB);

    size_t smem = (size_t)(4 * 64 * PADA + 3 * 64) * sizeof(float);  // ~70.4 KB
    cudaFuncSetAttribute(attn_kernel, cudaFuncAttributeMaxDynamicSharedMemorySize,
                         (int)smem);
    attn_kernel<<<dim3(Nq / 64, Hq, Bq), 256, smem>>>(mask);

    proj_gemm_kernel<<<dim3(Cq / 64, Mq / 64), 256>>>(W_proj, out);
}

// round 5
// speedup vs baseline: 1.4108x; 1.4108x over previous
#include <cuda_runtime.h>
#include <cuda_bf16.h>
#include <cstdint>
#include <math.h>

// Problem constants
#define Bq   4
#define Nq   2048
#define Cq   1024
#define Hq   16
#define Dq   64
#define Rq   16
#define Mq   (Bq*Nq)          // 8192 rows
#define C3q  (3*Cq)           // 3072
#define SCALEF 0.125f         // 1/sqrt(64)

// ---------------------------------------------------------------------------
// Device-global scratch (no cudaMalloc allowed)
// ---------------------------------------------------------------------------
__device__ float g_q [Mq*Cq];        // [B,H,N,D]
__device__ float g_k [Mq*Cq];
__device__ float g_v [Mq*Cq];
__device__ float g_ao[Mq*Cq];        // attention out, [B,N,C]

__device__ __nv_bfloat16 g_Ah[Mq*Cq],  g_Al[Mq*Cq];    // A split [M,K]
__device__ __nv_bfloat16 g_Bh[C3q*Cq], g_Bl[C3q*Cq];   // B^T split [N,K]
__device__ __nv_bfloat16 g_Ph[Mq*Rq],  g_Pl[Mq*Rq];    // lora P split [M,R]
__device__ __nv_bfloat16 g_WBh[Cq*Rq], g_WBl[Cq*Rq];   // (mag*W_loraB)^T split [C,R]

// ---------------------------------------------------------------------------
// mma.sync helpers (portable tensor-core path; tcgen05 PTX is rejected by the
// harness's compute_103 virtual arch)
// ---------------------------------------------------------------------------
__device__ __forceinline__ uint32_t smem_to_u32(const void* p) {
    uint32_t a;
    asm("{ .reg .u64 t; cvta.to.shared.u64 t, %1; cvt.u32.u64 %0, t; }"
        : "=r"(a) : "l"(p));
    return a;
}
__device__ __forceinline__ void ldsm_x4(uint32_t* r, uint32_t addr) {
    asm volatile("ldmatrix.sync.aligned.m8n8.x4.shared.b16 {%0,%1,%2,%3}, [%4];"
                 : "=r"(r[0]), "=r"(r[1]), "=r"(r[2]), "=r"(r[3]) : "r"(addr));
}
__device__ __forceinline__ void mma16816(float* c, const uint32_t* a, const uint32_t* b) {
    asm volatile("mma.sync.aligned.m16n8k16.row.col.f32.bf16.bf16.f32 "
        "{%0,%1,%2,%3}, {%4,%5,%6,%7}, {%8,%9}, {%0,%1,%2,%3};"
        : "+f"(c[0]), "+f"(c[1]), "+f"(c[2]), "+f"(c[3])
        : "r"(a[0]), "r"(a[1]), "r"(a[2]), "r"(a[3]), "r"(b[0]), "r"(b[1]));
}

// ---------------------------------------------------------------------------
// Conversion kernels
// ---------------------------------------------------------------------------
__global__ void split_kernel(const float* __restrict__ X,
                             __nv_bfloat16* __restrict__ H,
                             __nv_bfloat16* __restrict__ L) {
    int i = blockIdx.x * blockDim.x + threadIdx.x;   // over float4 units
    float4 x = ((const float4*)X)[i];
    __nv_bfloat16 h0 = __float2bfloat16(x.x), h1 = __float2bfloat16(x.y);
    __nv_bfloat16 h2 = __float2bfloat16(x.z), h3 = __float2bfloat16(x.w);
    __nv_bfloat16 l0 = __float2bfloat16(x.x - __bfloat162float(h0));
    __nv_bfloat16 l1 = __float2bfloat16(x.y - __bfloat162float(h1));
    __nv_bfloat16 l2 = __float2bfloat16(x.z - __bfloat162float(h2));
    __nv_bfloat16 l3 = __float2bfloat16(x.w - __bfloat162float(h3));
    ((__nv_bfloat162*)H)[2*i+0] = __nv_bfloat162(h0, h1);
    ((__nv_bfloat162*)H)[2*i+1] = __nv_bfloat162(h2, h3);
    ((__nv_bfloat162*)L)[2*i+0] = __nv_bfloat162(l0, l1);
    ((__nv_bfloat162*)L)[2*i+1] = __nv_bfloat162(l2, l3);
}

// W[K,N] fp32 -> BH/BL [N,K] bf16 (transpose + split). block (32,8), tile 32x32.
__global__ void transpose_split_kernel(const float* __restrict__ W,
                                       __nv_bfloat16* __restrict__ BH,
                                       __nv_bfloat16* __restrict__ BL,
                                       int K, int N) {
    __shared__ float tile[32][33];
    int n0 = blockIdx.x * 32, k0 = blockIdx.y * 32;
    int tx = threadIdx.x, ty = threadIdx.y;
#pragma unroll
    for (int i = 0; i < 4; i++)
        tile[ty + i * 8][tx] = W[(size_t)(k0 + ty + i * 8) * N + n0 + tx];
    __syncthreads();
#pragma unroll
    for (int i = 0; i < 4; i++) {
        int nl = ty + i * 8;
        float v = tile[tx][nl];
        __nv_bfloat16 h = __float2bfloat16(v);
        __nv_bfloat16 l = __float2bfloat16(v - __bfloat162float(h));
        size_t o = (size_t)(n0 + nl) * K + k0 + tx;
        BH[o] = h; BL[o] = l;
    }
}

// WB2t[n][r] = mag[n/64] * W_loraB[r][n], split
__global__ void wb2t_kernel(const float* __restrict__ WB,
                            const float* __restrict__ mag) {
    int idx = blockIdx.x * blockDim.x + threadIdx.x;   // 16384
    int r = idx >> 10, n = idx & 1023;
    float v = mag[n >> 6] * WB[r * Cq + n];
    __nv_bfloat16 h = __float2bfloat16(v);
    __nv_bfloat16 l = __float2bfloat16(v - __bfloat162float(h));
    g_WBh[n * Rq + r] = h;
    g_WBl[n * Rq + r] = l;
}

// ---------------------------------------------------------------------------
// Kernel: P = query @ W_loraA  -> bf16 split
// ---------------------------------------------------------------------------
__global__ void lora_p_kernel(const float* __restrict__ query,
                              const float* __restrict__ WA) {
    const int row  = blockIdx.x;
    const int tid  = threadIdx.x;
    const int lane = tid & 31;
    const int wid  = tid >> 5;

    float acc[Rq];
#pragma unroll
    for (int r = 0; r < Rq; r++) acc[r] = 0.f;

    const float* qr = query + (size_t)row * Cq;
    for (int c = tid; c < Cq; c += 256) {
        float qv = qr[c];
        const float4* wa = (const float4*)(WA + (size_t)c * Rq);
        float4 w0 = wa[0], w1 = wa[1], w2 = wa[2], w3 = wa[3];
        acc[0]  += qv * w0.x; acc[1]  += qv * w0.y; acc[2]  += qv * w0.z; acc[3]  += qv * w0.w;
        acc[4]  += qv * w1.x; acc[5]  += qv * w1.y; acc[6]  += qv * w1.z; acc[7]  += qv * w1.w;
        acc[8]  += qv * w2.x; acc[9]  += qv * w2.y; acc[10] += qv * w2.z; acc[11] += qv * w2.w;
        acc[12] += qv * w3.x; acc[13] += qv * w3.y; acc[14] += qv * w3.z; acc[15] += qv * w3.w;
    }
#pragma unroll
    for (int r = 0; r < Rq; r++) {
#pragma unroll
        for (int off = 16; off > 0; off >>= 1)
            acc[r] += __shfl_down_sync(0xffffffffu, acc[r], off);
    }
    __shared__ float part[8][Rq];
    if (lane == 0) {
#pragma unroll
        for (int r = 0; r < Rq; r++) part[wid][r] = acc[r];
    }
    __syncthreads();
    if (tid < Rq) {
        float s = 0.f;
#pragma unroll
        for (int w = 0; w < 8; w++) s += part[w][tid];
        __nv_bfloat16 h = __float2bfloat16(s);
        __nv_bfloat16 l = __float2bfloat16(s - __bfloat162float(h));
        g_Ph[(size_t)row * Rq + tid] = h;
        g_Pl[(size_t)row * Rq + tid] = l;
    }
}

// ---------------------------------------------------------------------------
// mma.sync split-bf16 GEMM. 128x128 CTA tile, 8 warps (2m x 4n), 64x32/warp.
// K processed in 64-wide blocks. MODE 0: qkv (scatter + DoRA extra k-step).
// MODE 1: proj (-> out).
// Smem: Ah/Al/Bh/Bl tiles [128][72] bf16 (pad 8 -> conflict-free ldmatrix).
// ---------------------------------------------------------------------------
#define LDSS   72
#define TILEB  (128 * LDSS)            // bf16 elems per buffer
#define SMEM_GEMM (4 * TILEB * 2)      // 73728 bytes

template<int MODE>
__global__ __launch_bounds__(256, 1) void mma_gemm_kernel(
    const __nv_bfloat16* __restrict__ Ah, const __nv_bfloat16* __restrict__ Al,
    const __nv_bfloat16* __restrict__ Bh, const __nv_bfloat16* __restrict__ Bl,
    float* __restrict__ out)
{
    extern __shared__ __nv_bfloat16 smb[];
    __nv_bfloat16* Ash = smb;
    __nv_bfloat16* Asl = smb + TILEB;
    __nv_bfloat16* Bsh = smb + 2 * TILEB;
    __nv_bfloat16* Bsl = smb + 3 * TILEB;
    const uint32_t sb   = smem_to_u32(smb);
    const uint32_t sbAl = sb + TILEB * 2;
    const uint32_t sbBh = sb + 2 * TILEB * 2;
    const uint32_t sbBl = sb + 3 * TILEB * 2;

    const int bn = blockIdx.x * 128;
    const int bm = blockIdx.y * 128;
    const int t    = threadIdx.x;
    const int lane = t & 31;
    const int wid  = t >> 5;
    const int wm = wid & 1, wn = wid >> 1;   // warp tile: rows wm*64.., cols wn*32..
    const bool is_q = (MODE == 0) && (bn < Cq);

    // ldmatrix per-lane row/col offsets
    const int a_row = lane & 15;
    const int a_col = (lane >> 4) << 3;                       // 0 or 8
    const int b_row = (lane & 7) + ((lane & 16) ? 8 : 0);
    const int b_col = (lane & 8);                             // 0 or 8

    float c[16][4];
#pragma unroll
    for (int i = 0; i < 16; i++)
#pragma unroll
        for (int j = 0; j < 4; j++) c[i][j] = 0.f;

    for (int kb = 0; kb < Cq / 64; kb++) {
        __syncthreads();
#pragma unroll
        for (int it = 0; it < 4; it++) {
            int idx = t + it * 256;                 // 0..1023
            int row = idx >> 3, ch = (idx & 7) * 8; // full 128x64 coverage
            size_t ga = (size_t)(bm + row) * Cq + kb * 64 + ch;
            size_t gb = (size_t)(bn + row) * Cq + kb * 64 + ch;
            *(uint4*)&Ash[row * LDSS + ch] = *(const uint4*)&Ah[ga];
            *(uint4*)&Asl[row * LDSS + ch] = *(const uint4*)&Al[ga];
            *(uint4*)&Bsh[row * LDSS + ch] = *(const uint4*)&Bh[gb];
            *(uint4*)&Bsl[row * LDSS + ch] = *(const uint4*)&Bl[gb];
        }
        __syncthreads();

#pragma unroll
        for (int k16 = 0; k16 < 4; k16++) {
            uint32_t ah[4][4], al[4][4];
#pragma unroll
            for (int fm = 0; fm < 4; fm++) {
                uint32_t off = 2u * (uint32_t)((wm * 64 + fm * 16 + a_row) * LDSS
                                               + k16 * 16 + a_col);
                ldsm_x4(ah[fm], sb   + off);
                ldsm_x4(al[fm], sbAl + off);
            }
#pragma unroll
            for (int fn2 = 0; fn2 < 2; fn2++) {
                uint32_t off = 2u * (uint32_t)((wn * 32 + fn2 * 16 + b_row) * LDSS
                                               + k16 * 16 + b_col);
                uint32_t bh4[4], bl4[4];
                ldsm_x4(bh4, sbBh + off);
                ldsm_x4(bl4, sbBl + off);
#pragma unroll
                for (int fm = 0; fm < 4; fm++) {
                    float* c0 = c[fm * 4 + fn2 * 2 + 0];
                    float* c1 = c[fm * 4 + fn2 * 2 + 1];
                    mma16816(c0, ah[fm], &bh4[0]);
                    mma16816(c1, ah[fm], &bh4[2]);
                    mma16816(c0, ah[fm], &bl4[0]);
                    mma16816(c1, ah[fm], &bl4[2]);
                    mma16816(c0, al[fm], &bh4[0]);
                    mma16816(c1, al[fm], &bh4[2]);
                }
            }
        }
    }

    // DoRA extra k16 step (q tiles only): A = P[128x16], B = (mag*WB)^T[128x16]
    if (is_q) {
        __syncthreads();
        {
            int row = t >> 1, ch = (t & 1) * 8;
            *(uint4*)&Ash[row * LDSS + ch] = *(const uint4*)&g_Ph [(size_t)(bm + row) * Rq + ch];
            *(uint4*)&Asl[row * LDSS + ch] = *(const uint4*)&g_Pl [(size_t)(bm + row) * Rq + ch];
            *(uint4*)&Bsh[row * LDSS + ch] = *(const uint4*)&g_WBh[(size_t)(bn + row) * Rq + ch];
            *(uint4*)&Bsl[row * LDSS + ch] = *(const uint4*)&g_WBl[(size_t)(bn + row) * Rq + ch];
        }
        __syncthreads();
        uint32_t ah[4][4], al[4][4];
#pragma unroll
        for (int fm = 0; fm < 4; fm++) {
            uint32_t off = 2u * (uint32_t)((wm * 64 + fm * 16 + a_row) * LDSS + a_col);
            ldsm_x4(ah[fm], sb   + off);
            ldsm_x4(al[fm], sbAl + off);
        }
#pragma unroll
        for (int fn2 = 0; fn2 < 2; fn2++) {
            uint32_t off = 2u * (uint32_t)((wn * 32 + fn2 * 16 + b_row) * LDSS + b_col);
            uint32_t bh4[4], bl4[4];
            ldsm_x4(bh4, sbBh + off);
            ldsm_x4(bl4, sbBl + off);
#pragma unroll
            for (int fm = 0; fm < 4; fm++) {
                float* c0 = c[fm * 4 + fn2 * 2 + 0];
                float* c1 = c[fm * 4 + fn2 * 2 + 1];
                mma16816(c0, ah[fm], &bh4[0]);
                mma16816(c1, ah[fm], &bh4[2]);
                mma16816(c0, ah[fm], &bl4[0]);
                mma16816(c1, ah[fm], &bl4[2]);
                mma16816(c0, al[fm], &bh4[0]);
                mma16816(c1, al[fm], &bh4[2]);
            }
        }
    }

    // Epilogue: scatter C fragments
#pragma unroll
    for (int fm = 0; fm < 4; fm++) {
#pragma unroll
        for (int fn = 0; fn < 4; fn++) {
            const float* cc = c[fm * 4 + fn];
            int r0  = bm + wm * 64 + fm * 16 + (lane >> 2);
            int col = bn + wn * 32 + fn * 8 + (lane & 3) * 2;
#pragma unroll
            for (int half = 0; half < 2; half++) {
                int m = r0 + half * 8;
                float2 v = make_float2(cc[half * 2 + 0], cc[half * 2 + 1]);
                if (MODE == 1) {
                    *(float2*)(out + (size_t)m * Cq + col) = v;
                } else {
                    int sel = col >> 10;
                    int within = col & (Cq - 1);
                    int h = within >> 6, d = within & 63;
                    int b = m >> 11, n = m & (Nq - 1);
                    float* basep = (sel == 0) ? g_q : (sel == 1) ? g_k : g_v;
                    *(float2*)(basep + ((((size_t)b * Hq + h) * Nq) + n) * Dq + d) = v;
                }
            }
        }
    }
}

// ---------------------------------------------------------------------------
// Kernel 3: flash attention (fp32, online softmax) — unchanged
// ---------------------------------------------------------------------------
#define PADA 68
__global__ void attn_kernel(const float* __restrict__ mask) {
    extern __shared__ float sm[];
    float* Qs = sm;
    float* Ks = Qs + 64 * PADA;
    float* Vs = Ks + 64 * PADA;
    float* Ps = Vs + 64 * PADA;
    float* mrow = Ps + 64 * PADA;
    float* lrow = mrow + 64;
    float* rsrow = lrow + 64;

    const int qt = blockIdx.x, h = blockIdx.y, b = blockIdx.z;
    const int t  = threadIdx.x;
    const int tx = t & 15, ty = t >> 4;

    const size_t base = ((size_t)b * Hq + h) * Nq;
    const float* Qg = g_q + (base + (size_t)qt * 64) * Dq;

#pragma unroll
    for (int it = 0; it < 4; it++) {
        int idx = t + it * 256;
        int r = idx >> 4, d4 = (idx & 15) * 4;
        *(float4*)&Qs[r * PADA + d4] = *(const float4*)(Qg + r * Dq + d4);
    }
    if (t < 64) { mrow[t] = -1e30f; lrow[t] = 0.f; }

    float o[4][4] = {};
    const float* maskb = mask + (size_t)b * Nq * Nq + (size_t)(qt * 64) * Nq;

    for (int kt = 0; kt < Nq / 64; kt++) {
        __syncthreads();
        const float* Kg = g_k + (base + (size_t)kt * 64) * Dq;
        const float* Vg = g_v + (base + (size_t)kt * 64) * Dq;
#pragma unroll
        for (int it = 0; it < 4; it++) {
            int idx = t + it * 256;
            int cidx = idx >> 4, d4 = (idx & 15) * 4;
            float4 kv = *(const float4*)(Kg + cidx * Dq + d4);
            Ks[(d4 + 0) * PADA + cidx] = kv.x;
            Ks[(d4 + 1) * PADA + cidx] = kv.y;
            Ks[(d4 + 2) * PADA + cidx] = kv.z;
            Ks[(d4 + 3) * PADA + cidx] = kv.w;
            *(float4*)&Vs[cidx * PADA + d4] = *(const float4*)(Vg + cidx * Dq + d4);
        }
        __syncthreads();

        float s[4][4] = {};
#pragma unroll
        for (int k = 0; k < 64; k++) {
            float ar[4], br[4];
#pragma unroll
            for (int i = 0; i < 4; i++) ar[i] = Qs[(ty * 4 + i) * PADA + k];
#pragma unroll
            for (int j = 0; j < 4; j++) br[j] = Ks[k * PADA + tx * 4 + j];
#pragma unroll
            for (int i = 0; i < 4; i++)
#pragma unroll
                for (int j = 0; j < 4; j++) s[i][j] += ar[i] * br[j];
        }
#pragma unroll
        for (int i = 0; i < 4; i++) {
            const float* mg = maskb + (size_t)(ty * 4 + i) * Nq + kt * 64 + tx * 4;
            float4 m4 = *(const float4*)mg;
            float4 sv;
            sv.x = s[i][0] * SCALEF + m4.x;
            sv.y = s[i][1] * SCALEF + m4.y;
            sv.z = s[i][2] * SCALEF + m4.z;
            sv.w = s[i][3] * SCALEF + m4.w;
            *(float4*)&Ps[(ty * 4 + i) * PADA + tx * 4] = sv;
        }
        __syncthreads();

        if (t < 64) {
            float* pr = Ps + t * PADA;
            float mx = mrow[t];
#pragma unroll
            for (int j = 0; j < 64; j++) mx = fmaxf(mx, pr[j]);
            float sc = __expf(mrow[t] - mx);
            float sum = 0.f;
#pragma unroll
            for (int j = 0; j < 64; j++) {
                float p = __expf(pr[j] - mx);
                pr[j] = p;
                sum += p;
            }
            lrow[t] = lrow[t] * sc + sum;
            mrow[t] = mx;
            rsrow[t] = sc;
        }
        __syncthreads();

        float rs[4];
#pragma unroll
        for (int i = 0; i < 4; i++) rs[i] = rsrow[ty * 4 + i];
#pragma unroll
        for (int i = 0; i < 4; i++)
#pragma unroll
            for (int j = 0; j < 4; j++) o[i][j] *= rs[i];
#pragma unroll
        for (int jj = 0; jj < 64; jj++) {
            float pv[4], vv[4];
#pragma unroll
            for (int i = 0; i < 4; i++) pv[i] = Ps[(ty * 4 + i) * PADA + jj];
#pragma unroll
            for (int j = 0; j < 4; j++) vv[j] = Vs[jj * PADA + tx * 4 + j];
#pragma unroll
            for (int i = 0; i < 4; i++)
#pragma unroll
                for (int j = 0; j < 4; j++) o[i][j] += pv[i] * vv[j];
        }
    }

#pragma unroll
    for (int i = 0; i < 4; i++) {
        int r = ty * 4 + i;
        float inv = 1.0f / lrow[r];
        int n = qt * 64 + r;
        float* op = g_ao + ((size_t)(b * Nq + n)) * Cq + h * Dq + tx * 4;
        float4 ov;
        ov.x = o[i][0] * inv; ov.y = o[i][1] * inv;
        ov.z = o[i][2] * inv; ov.w = o[i][3] * inv;
        *(float4*)op = ov;
    }
}

// ---------------------------------------------------------------------------
extern "C" void kernel_launch(void* const* d_in, const int* in_sizes, int n_in,
                              void* d_out, int out_size) {
    const float* query     = (const float*)d_in[0];
    const float* mask      = (const float*)d_in[1];
    const float* W_qkv     = (const float*)d_in[2];
    const float* magnitude = (const float*)d_in[3];
    const float* W_loraA   = (const float*)d_in[4];
    const float* W_loraB   = (const float*)d_in[5];
    const float* W_proj    = (const float*)d_in[6];
    float* out = (float*)d_out;

    cudaFuncSetAttribute(mma_gemm_kernel<0>,
        cudaFuncAttributeMaxDynamicSharedMemorySize, SMEM_GEMM);
    cudaFuncSetAttribute(mma_gemm_kernel<1>,
        cudaFuncAttributeMaxDynamicSharedMemorySize, SMEM_GEMM);
    cudaFuncSetAttribute(attn_kernel,
        cudaFuncAttributeMaxDynamicSharedMemorySize,
        (int)((4 * 64 * PADA + 3 * 64) * sizeof(float)));

    __nv_bfloat16 *gAh, *gAl, *gBh, *gBl;
    float *gao;
    cudaGetSymbolAddress((void**)&gAh, g_Ah);
    cudaGetSymbolAddress((void**)&gAl, g_Al);
    cudaGetSymbolAddress((void**)&gBh, g_Bh);
    cudaGetSymbolAddress((void**)&gBl, g_Bl);
    cudaGetSymbolAddress((void**)&gao, g_ao);   // FIX: device address, not host shadow

    // Stage 1: conversions + lora
    split_kernel<<<(Mq * Cq / 4) / 256, 256>>>(query, gAh, gAl);
    transpose_split_kernel<<<dim3(C3q / 32, Cq / 32), dim3(32, 8)>>>(W_qkv, gBh, gBl, Cq, C3q);
    wb2t_kernel<<<64, 256>>>(W_loraB, magnitude);
    lora_p_kernel<<<Mq, 256>>>(query, W_loraA);

    // Stage 2: qkv GEMM on tensor cores (DoRA fused as extra k-step)
    mma_gemm_kernel<0><<<dim3(C3q / 128, Mq / 128), 256, SMEM_GEMM>>>(gAh, gAl, gBh, gBl, nullptr);

    // Stage 3: attention (fp32 SIMT flash)
    size_t smem = (size_t)(4 * 64 * PADA + 3 * 64) * sizeof(float);
    attn_kernel<<<dim3(Nq / 64, Hq, Bq), 256, smem>>>(mask);

    // Stage 4: proj GEMM on tensor cores
    split_kernel<<<(Mq * Cq / 4) / 256, 256>>>(gao, gAh, gAl);
    transpose_split_kernel<<<dim3(Cq / 32, Cq / 32), dim3(32, 8)>>>(W_proj, gBh, gBl, Cq, Cq);
    mma_gemm_kernel<1><<<dim3(Cq / 128, Mq / 128), 256, SMEM_GEMM>>>(gAh, gAl, gBh, gBl, out);
}

// round 6
// speedup vs baseline: 2.5177x; 1.7845x over previous
#include <cuda_runtime.h>
#include <cuda_bf16.h>
#include <cstdint>
#include <math.h>

// Problem constants
#define Bq   4
#define Nq   2048
#define Cq   1024
#define Hq   16
#define Dq   64
#define Rq   16
#define Mq   (Bq*Nq)          // 8192 rows
#define C3q  (3*Cq)           // 3072
#define SCALEF 0.125f         // 1/sqrt(64)

// ---------------------------------------------------------------------------
// Device-global scratch (no cudaMalloc allowed). All attention operands live
// as split bf16 (hi + lo); fp32 intermediates eliminated.
// ---------------------------------------------------------------------------
__device__ __nv_bfloat16 g_qh[Mq*Cq], g_ql[Mq*Cq];    // q  [B,H,N,D]
__device__ __nv_bfloat16 g_kh[Mq*Cq], g_kl[Mq*Cq];    // k
__device__ __nv_bfloat16 g_vh[Mq*Cq], g_vl[Mq*Cq];    // v
__device__ __nv_bfloat16 g_aoh[Mq*Cq], g_aol[Mq*Cq];  // attn out [B,N,C] split

__device__ __nv_bfloat16 g_Ah[Mq*Cq],  g_Al[Mq*Cq];    // qkv A split [M,K]
__device__ __nv_bfloat16 g_Bh[C3q*Cq], g_Bl[C3q*Cq];   // W^T split [N,K]
__device__ __nv_bfloat16 g_Ph[Mq*Rq],  g_Pl[Mq*Rq];    // lora P split [M,R]
__device__ __nv_bfloat16 g_WBh[Cq*Rq], g_WBl[Cq*Rq];   // (mag*W_loraB)^T split

// ---------------------------------------------------------------------------
// mma.sync helpers
// ---------------------------------------------------------------------------
__device__ __forceinline__ uint32_t smem_to_u32(const void* p) {
    uint32_t a;
    asm("{ .reg .u64 t; cvta.to.shared.u64 t, %1; cvt.u32.u64 %0, t; }"
        : "=r"(a) : "l"(p));
    return a;
}
__device__ __forceinline__ void ldsm_x4(uint32_t* r, uint32_t addr) {
    asm volatile("ldmatrix.sync.aligned.m8n8.x4.shared.b16 {%0,%1,%2,%3}, [%4];"
                 : "=r"(r[0]), "=r"(r[1]), "=r"(r[2]), "=r"(r[3]) : "r"(addr));
}
__device__ __forceinline__ void ldsm_x4_t(uint32_t* r, uint32_t addr) {
    asm volatile("ldmatrix.sync.aligned.m8n8.x4.trans.shared.b16 {%0,%1,%2,%3}, [%4];"
                 : "=r"(r[0]), "=r"(r[1]), "=r"(r[2]), "=r"(r[3]) : "r"(addr));
}
__device__ __forceinline__ void mma16816(float* c, const uint32_t* a, const uint32_t* b) {
    asm volatile("mma.sync.aligned.m16n8k16.row.col.f32.bf16.bf16.f32 "
        "{%0,%1,%2,%3}, {%4,%5,%6,%7}, {%8,%9}, {%0,%1,%2,%3};"
        : "+f"(c[0]), "+f"(c[1]), "+f"(c[2]), "+f"(c[3])
        : "r"(a[0]), "r"(a[1]), "r"(a[2]), "r"(a[3]), "r"(b[0]), "r"(b[1]));
}
// split two fp32 into packed bf16 hi / lo pairs
__device__ __forceinline__ void split2(float x, float y, uint32_t& hi, uint32_t& lo) {
    __nv_bfloat16 hx = __float2bfloat16(x), hy = __float2bfloat16(y);
    __nv_bfloat16 lx = __float2bfloat16(x - __bfloat162float(hx));
    __nv_bfloat16 ly = __float2bfloat16(y - __bfloat162float(hy));
    __nv_bfloat162 H(hx, hy), L(lx, ly);
    hi = *(uint32_t*)&H; lo = *(uint32_t*)&L;
}

// ---------------------------------------------------------------------------
// Conversion kernels
// ---------------------------------------------------------------------------
__global__ void split_kernel(const float* __restrict__ X,
                             __nv_bfloat16* __restrict__ H,
                             __nv_bfloat16* __restrict__ L) {
    int i = blockIdx.x * blockDim.x + threadIdx.x;
    float4 x = ((const float4*)X)[i];
    uint32_t h0, l0, h1, l1;
    split2(x.x, x.y, h0, l0);
    split2(x.z, x.w, h1, l1);
    ((uint32_t*)H)[2*i+0] = h0; ((uint32_t*)H)[2*i+1] = h1;
    ((uint32_t*)L)[2*i+0] = l0; ((uint32_t*)L)[2*i+1] = l1;
}

__global__ void transpose_split_kernel(const float* __restrict__ W,
                                       __nv_bfloat16* __restrict__ BH,
                                       __nv_bfloat16* __restrict__ BL,
                                       int K, int N) {
    __shared__ float tile[32][33];
    int n0 = blockIdx.x * 32, k0 = blockIdx.y * 32;
    int tx = threadIdx.x, ty = threadIdx.y;
#pragma unroll
    for (int i = 0; i < 4; i++)
        tile[ty + i * 8][tx] = W[(size_t)(k0 + ty + i * 8) * N + n0 + tx];
    __syncthreads();
#pragma unroll
    for (int i = 0; i < 4; i++) {
        int nl = ty + i * 8;
        float v = tile[tx][nl];
        __nv_bfloat16 h = __float2bfloat16(v);
        __nv_bfloat16 l = __float2bfloat16(v - __bfloat162float(h));
        size_t o = (size_t)(n0 + nl) * K + k0 + tx;
        BH[o] = h; BL[o] = l;
    }
}

__global__ void wb2t_kernel(const float* __restrict__ WB,
                            const float* __restrict__ mag) {
    int idx = blockIdx.x * blockDim.x + threadIdx.x;
    int r = idx >> 10, n = idx & 1023;
    float v = mag[n >> 6] * WB[r * Cq + n];
    __nv_bfloat16 h = __float2bfloat16(v);
    __nv_bfloat16 l = __float2bfloat16(v - __bfloat162float(h));
    g_WBh[n * Rq + r] = h;
    g_WBl[n * Rq + r] = l;
}

__global__ void lora_p_kernel(const float* __restrict__ query,
                              const float* __restrict__ WA) {
    const int row  = blockIdx.x;
    const int tid  = threadIdx.x;
    const int lane = tid & 31;
    const int wid  = tid >> 5;

    float acc[Rq];
#pragma unroll
    for (int r = 0; r < Rq; r++) acc[r] = 0.f;

    const float* qr = query + (size_t)row * Cq;
    for (int c = tid; c < Cq; c += 256) {
        float qv = qr[c];
        const float4* wa = (const float4*)(WA + (size_t)c * Rq);
        float4 w0 = wa[0], w1 = wa[1], w2 = wa[2], w3 = wa[3];
        acc[0]  += qv * w0.x; acc[1]  += qv * w0.y; acc[2]  += qv * w0.z; acc[3]  += qv * w0.w;
        acc[4]  += qv * w1.x; acc[5]  += qv * w1.y; acc[6]  += qv * w1.z; acc[7]  += qv * w1.w;
        acc[8]  += qv * w2.x; acc[9]  += qv * w2.y; acc[10] += qv * w2.z; acc[11] += qv * w2.w;
        acc[12] += qv * w3.x; acc[13] += qv * w3.y; acc[14] += qv * w3.z; acc[15] += qv * w3.w;
    }
#pragma unroll
    for (int r = 0; r < Rq; r++) {
#pragma unroll
        for (int off = 16; off > 0; off >>= 1)
            acc[r] += __shfl_down_sync(0xffffffffu, acc[r], off);
    }
    __shared__ float part[8][Rq];
    if (lane == 0) {
#pragma unroll
        for (int r = 0; r < Rq; r++) part[wid][r] = acc[r];
    }
    __syncthreads();
    if (tid < Rq) {
        float s = 0.f;
#pragma unroll
        for (int w = 0; w < 8; w++) s += part[w][tid];
        __nv_bfloat16 h = __float2bfloat16(s);
        __nv_bfloat16 l = __float2bfloat16(s - __bfloat162float(h));
        g_Ph[(size_t)row * Rq + tid] = h;
        g_Pl[(size_t)row * Rq + tid] = l;
    }
}

// ---------------------------------------------------------------------------
// mma.sync split-bf16 GEMM (as in round 5). MODE 0: qkv -> split-bf16 q/k/v.
// MODE 1: proj -> fp32 out.
// ---------------------------------------------------------------------------
#define LDSS   72
#define TILEB  (128 * LDSS)
#define SMEM_GEMM (4 * TILEB * 2)

template<int MODE>
__global__ __launch_bounds__(256, 1) void mma_gemm_kernel(
    const __nv_bfloat16* __restrict__ Ah, const __nv_bfloat16* __restrict__ Al,
    const __nv_bfloat16* __restrict__ Bh, const __nv_bfloat16* __restrict__ Bl,
    float* __restrict__ out)
{
    extern __shared__ __nv_bfloat16 smb[];
    __nv_bfloat16* Ash = smb;
    __nv_bfloat16* Asl = smb + TILEB;
    __nv_bfloat16* Bsh = smb + 2 * TILEB;
    __nv_bfloat16* Bsl = smb + 3 * TILEB;
    const uint32_t sb   = smem_to_u32(smb);
    const uint32_t sbAl = sb + TILEB * 2;
    const uint32_t sbBh = sb + 2 * TILEB * 2;
    const uint32_t sbBl = sb + 3 * TILEB * 2;

    const int bn = blockIdx.x * 128;
    const int bm = blockIdx.y * 128;
    const int t    = threadIdx.x;
    const int lane = t & 31;
    const int wid  = t >> 5;
    const int wm = wid & 1, wn = wid >> 1;
    const bool is_q = (MODE == 0) && (bn < Cq);

    const int a_row = lane & 15;
    const int a_col = (lane >> 4) << 3;
    const int b_row = (lane & 7) + ((lane & 16) ? 8 : 0);
    const int b_col = (lane & 8);

    float c[16][4];
#pragma unroll
    for (int i = 0; i < 16; i++)
#pragma unroll
        for (int j = 0; j < 4; j++) c[i][j] = 0.f;

    for (int kb = 0; kb < Cq / 64; kb++) {
        __syncthreads();
#pragma unroll
        for (int it = 0; it < 4; it++) {
            int idx = t + it * 256;
            int row = idx >> 3, ch = (idx & 7) * 8;
            size_t ga = (size_t)(bm + row) * Cq + kb * 64 + ch;
            size_t gb = (size_t)(bn + row) * Cq + kb * 64 + ch;
            *(uint4*)&Ash[row * LDSS + ch] = *(const uint4*)&Ah[ga];
            *(uint4*)&Asl[row * LDSS + ch] = *(const uint4*)&Al[ga];
            *(uint4*)&Bsh[row * LDSS + ch] = *(const uint4*)&Bh[gb];
            *(uint4*)&Bsl[row * LDSS + ch] = *(const uint4*)&Bl[gb];
        }
        __syncthreads();

#pragma unroll
        for (int k16 = 0; k16 < 4; k16++) {
            uint32_t ah[4][4], al[4][4];
#pragma unroll
            for (int fm = 0; fm < 4; fm++) {
                uint32_t off = 2u * (uint32_t)((wm * 64 + fm * 16 + a_row) * LDSS
                                               + k16 * 16 + a_col);
                ldsm_x4(ah[fm], sb   + off);
                ldsm_x4(al[fm], sbAl + off);
            }
#pragma unroll
            for (int fn2 = 0; fn2 < 2; fn2++) {
                uint32_t off = 2u * (uint32_t)((wn * 32 + fn2 * 16 + b_row) * LDSS
                                               + k16 * 16 + b_col);
                uint32_t bh4[4], bl4[4];
                ldsm_x4(bh4, sbBh + off);
                ldsm_x4(bl4, sbBl + off);
#pragma unroll
                for (int fm = 0; fm < 4; fm++) {
                    float* c0 = c[fm * 4 + fn2 * 2 + 0];
                    float* c1 = c[fm * 4 + fn2 * 2 + 1];
                    mma16816(c0, ah[fm], &bh4[0]);
                    mma16816(c1, ah[fm], &bh4[2]);
                    mma16816(c0, ah[fm], &bl4[0]);
                    mma16816(c1, ah[fm], &bl4[2]);
                    mma16816(c0, al[fm], &bh4[0]);
                    mma16816(c1, al[fm], &bh4[2]);
                }
            }
        }
    }

    // DoRA extra k16 step (q tiles only)
    if (is_q) {
        __syncthreads();
        {
            int row = t >> 1, ch = (t & 1) * 8;
            *(uint4*)&Ash[row * LDSS + ch] = *(const uint4*)&g_Ph [(size_t)(bm + row) * Rq + ch];
            *(uint4*)&Asl[row * LDSS + ch] = *(const uint4*)&g_Pl [(size_t)(bm + row) * Rq + ch];
            *(uint4*)&Bsh[row * LDSS + ch] = *(const uint4*)&g_WBh[(size_t)(bn + row) * Rq + ch];
            *(uint4*)&Bsl[row * LDSS + ch] = *(const uint4*)&g_WBl[(size_t)(bn + row) * Rq + ch];
        }
        __syncthreads();
        uint32_t ah[4][4], al[4][4];
#pragma unroll
        for (int fm = 0; fm < 4; fm++) {
            uint32_t off = 2u * (uint32_t)((wm * 64 + fm * 16 + a_row) * LDSS + a_col);
            ldsm_x4(ah[fm], sb   + off);
            ldsm_x4(al[fm], sbAl + off);
        }
#pragma unroll
        for (int fn2 = 0; fn2 < 2; fn2++) {
            uint32_t off = 2u * (uint32_t)((wn * 32 + fn2 * 16 + b_row) * LDSS + b_col);
            uint32_t bh4[4], bl4[4];
            ldsm_x4(bh4, sbBh + off);
            ldsm_x4(bl4, sbBl + off);
#pragma unroll
            for (int fm = 0; fm < 4; fm++) {
                float* c0 = c[fm * 4 + fn2 * 2 + 0];
                float* c1 = c[fm * 4 + fn2 * 2 + 1];
                mma16816(c0, ah[fm], &bh4[0]);
                mma16816(c1, ah[fm], &bh4[2]);
                mma16816(c0, ah[fm], &bl4[0]);
                mma16816(c1, ah[fm], &bl4[2]);
                mma16816(c0, al[fm], &bh4[0]);
                mma16816(c1, al[fm], &bh4[2]);
            }
        }
    }

    // Epilogue
#pragma unroll
    for (int fm = 0; fm < 4; fm++) {
#pragma unroll
        for (int fn = 0; fn < 4; fn++) {
            const float* cc = c[fm * 4 + fn];
            int r0  = bm + wm * 64 + fm * 16 + (lane >> 2);
            int col = bn + wn * 32 + fn * 8 + (lane & 3) * 2;
#pragma unroll
            for (int half = 0; half < 2; half++) {
                int m = r0 + half * 8;
                float vx = cc[half * 2 + 0], vy = cc[half * 2 + 1];
                if (MODE == 1) {
                    *(float2*)(out + (size_t)m * Cq + col) = make_float2(vx, vy);
                } else {
                    int sel = col >> 10;
                    int within = col & (Cq - 1);
                    int h = within >> 6, d = within & 63;
                    int b = m >> 11, n = m & (Nq - 1);
                    size_t oidx = ((((size_t)b * Hq + h) * Nq) + n) * Dq + d;
                    uint32_t hi, lo;
                    split2(vx, vy, hi, lo);
                    __nv_bfloat16 *ph, *pl;
                    if (sel == 0)      { ph = g_qh; pl = g_ql; }
                    else if (sel == 1) { ph = g_kh; pl = g_kl; }
                    else               { ph = g_vh; pl = g_vl; }
                    *(uint32_t*)&ph[oidx] = hi;
                    *(uint32_t*)&pl[oidx] = lo;
                }
            }
        }
    }
}

// ---------------------------------------------------------------------------
// Flash attention on mma.sync, split-bf16. Block = (h, qtile-128, b), 8 warps,
// warp w owns q rows w*16..w*16+15 (full 64-wide K tile) -> row stats are
// intra-warp (shuffle over lane%4 quad). P repack C->A is register-only.
// V consumed via ldmatrix.x4.trans from [token][d] smem.
// ---------------------------------------------------------------------------
#define ALDS 72
#define SMEM_ATTN (512 * ALDS * 2)   // 73728 B

__global__ __launch_bounds__(256, 1) void attn_mma_kernel(const float* __restrict__ mask) {
    extern __shared__ __nv_bfloat16 sma[];
    __nv_bfloat16* Qh = sma;                    // [128][ALDS]
    __nv_bfloat16* Ql = sma + 128 * ALDS;
    __nv_bfloat16* Kh = sma + 256 * ALDS;       // [64][ALDS]
    __nv_bfloat16* Kl = sma + 320 * ALDS;
    __nv_bfloat16* Vh = sma + 384 * ALDS;       // [64][ALDS]
    __nv_bfloat16* Vl = sma + 448 * ALDS;
    const uint32_t sbQh = smem_to_u32(sma);
    const uint32_t sbQl = sbQh + 128 * ALDS * 2;
    const uint32_t sbKh = sbQh + 256 * ALDS * 2;
    const uint32_t sbKl = sbQh + 320 * ALDS * 2;
    const uint32_t sbVh = sbQh + 384 * ALDS * 2;
    const uint32_t sbVl = sbQh + 448 * ALDS * 2;

    const int h  = blockIdx.x, qt = blockIdx.y, b = blockIdx.z;
    const int t    = threadIdx.x;
    const int lane = t & 31;
    const int wid  = t >> 5;

    const size_t base = ((size_t)b * Hq + h) * Nq;  // token base for this (b,h)
    const __nv_bfloat16* Qgh = g_qh + (base + (size_t)qt * 128) * Dq;
    const __nv_bfloat16* Qgl = g_ql + (base + (size_t)qt * 128) * Dq;

    // Load Q tile (128 x 64, hi+lo)
#pragma unroll
    for (int it = 0; it < 4; it++) {
        int idx = t + it * 256;                  // 0..1023
        int row = idx >> 3, ch = (idx & 7) * 8;
        *(uint4*)&Qh[row * ALDS + ch] = *(const uint4*)&Qgh[row * Dq + ch];
        *(uint4*)&Ql[row * ALDS + ch] = *(const uint4*)&Qgl[row * Dq + ch];
    }
    __syncthreads();

    // Preload Q A-fragments (4 k16 steps over d)
    const int a_row = lane & 15;
    const int a_col = (lane >> 4) << 3;
    uint32_t aQh[4][4], aQl[4][4];
#pragma unroll
    for (int kk = 0; kk < 4; kk++) {
        uint32_t off = 2u * (uint32_t)((wid * 16 + a_row) * ALDS + kk * 16 + a_col);
        ldsm_x4(aQh[kk], sbQh + off);
        ldsm_x4(aQl[kk], sbQl + off);
    }

    const int b_row = (lane & 7) + ((lane & 16) ? 8 : 0);
    const int b_col = (lane & 8);
    const int v_row = lane & 15;
    const int v_col = (lane & 16) ? 8 : 0;

    float o[8][4];
#pragma unroll
    for (int i = 0; i < 8; i++)
#pragma unroll
        for (int j = 0; j < 4; j++) o[i][j] = 0.f;
    float m0 = -1e30f, m1 = -1e30f, l0 = 0.f, l1 = 0.f;

    const float* maskrow = mask + (size_t)b * Nq * Nq
                         + (size_t)(qt * 128 + wid * 16 + (lane >> 2)) * Nq;

    for (int kt = 0; kt < Nq / 64; kt++) {
        __syncthreads();   // protect K/V smem from previous iteration readers
#pragma unroll
        for (int it = 0; it < 2; it++) {
            int idx = t + it * 256;              // 0..511
            int row = idx >> 3, ch = (idx & 7) * 8;
            size_t g = (base + (size_t)(kt * 64 + row)) * Dq + ch;
            *(uint4*)&Kh[row * ALDS + ch] = *(const uint4*)&g_kh[g];
            *(uint4*)&Kl[row * ALDS + ch] = *(const uint4*)&g_kl[g];
            *(uint4*)&Vh[row * ALDS + ch] = *(const uint4*)&g_vh[g];
            *(uint4*)&Vl[row * ALDS + ch] = *(const uint4*)&g_vl[g];
        }
        __syncthreads();

        // S = Q K^T (16 x 64 per warp), 3-term split
        float c[8][4];
#pragma unroll
        for (int i = 0; i < 8; i++)
#pragma unroll
            for (int j = 0; j < 4; j++) c[i][j] = 0.f;
#pragma unroll
        for (int fn2 = 0; fn2 < 4; fn2++) {
#pragma unroll
            for (int kk = 0; kk < 4; kk++) {
                uint32_t off = 2u * (uint32_t)((fn2 * 16 + b_row) * ALDS + kk * 16 + b_col);
                uint32_t bh4[4], bl4[4];
                ldsm_x4(bh4, sbKh + off);
                ldsm_x4(bl4, sbKl + off);
                float* c0 = c[fn2 * 2 + 0];
                float* c1 = c[fn2 * 2 + 1];
                mma16816(c0, aQh[kk], &bh4[0]);
                mma16816(c1, aQh[kk], &bh4[2]);
                mma16816(c0, aQh[kk], &bl4[0]);
                mma16816(c1, aQh[kk], &bl4[2]);
                mma16816(c0, aQl[kk], &bh4[0]);
                mma16816(c1, aQl[kk], &bh4[2]);
            }
        }

        // scale + mask
        const int colbase = kt * 64 + 2 * (lane & 3);
#pragma unroll
        for (int f = 0; f < 8; f++) {
            float2 mk0 = *(const float2*)&maskrow[colbase + f * 8];
            float2 mk1 = *(const float2*)&maskrow[8 * Nq + colbase + f * 8];
            c[f][0] = c[f][0] * SCALEF + mk0.x;
            c[f][1] = c[f][1] * SCALEF + mk0.y;
            c[f][2] = c[f][2] * SCALEF + mk1.x;
            c[f][3] = c[f][3] * SCALEF + mk1.y;
        }

        // online softmax (rows lane/4 and lane/4+8; quad = lanes sharing row)
        float rm0 = -1e30f, rm1 = -1e30f;
#pragma unroll
        for (int f = 0; f < 8; f++) {
            rm0 = fmaxf(rm0, fmaxf(c[f][0], c[f][1]));
            rm1 = fmaxf(rm1, fmaxf(c[f][2], c[f][3]));
        }
        rm0 = fmaxf(rm0, __shfl_xor_sync(0xffffffffu, rm0, 1));
        rm0 = fmaxf(rm0, __shfl_xor_sync(0xffffffffu, rm0, 2));
        rm1 = fmaxf(rm1, __shfl_xor_sync(0xffffffffu, rm1, 1));
        rm1 = fmaxf(rm1, __shfl_xor_sync(0xffffffffu, rm1, 2));
        float nm0 = fmaxf(m0, rm0), nm1 = fmaxf(m1, rm1);
        float sc0 = __expf(m0 - nm0), sc1 = __expf(m1 - nm1);
        float s0 = 0.f, s1 = 0.f;
#pragma unroll
        for (int f = 0; f < 8; f++) {
            c[f][0] = __expf(c[f][0] - nm0);
            c[f][1] = __expf(c[f][1] - nm0);
            c[f][2] = __expf(c[f][2] - nm1);
            c[f][3] = __expf(c[f][3] - nm1);
            s0 += c[f][0] + c[f][1];
            s1 += c[f][2] + c[f][3];
        }
        s0 += __shfl_xor_sync(0xffffffffu, s0, 1);
        s0 += __shfl_xor_sync(0xffffffffu, s0, 2);
        s1 += __shfl_xor_sync(0xffffffffu, s1, 1);
        s1 += __shfl_xor_sync(0xffffffffu, s1, 2);
        l0 = l0 * sc0 + s0; m0 = nm0;
        l1 = l1 * sc1 + s1; m1 = nm1;
#pragma unroll
        for (int f = 0; f < 8; f++) {
            o[f][0] *= sc0; o[f][1] *= sc0;
            o[f][2] *= sc1; o[f][3] *= sc1;
        }

        // O += P V : per k16 token step, repack P (C->A, register-only) + split
#pragma unroll
        for (int kk = 0; kk < 4; kk++) {
            uint32_t pah[4], pal[4];
            split2(c[2*kk  ][0], c[2*kk  ][1], pah[0], pal[0]);
            split2(c[2*kk  ][2], c[2*kk  ][3], pah[1], pal[1]);
            split2(c[2*kk+1][0], c[2*kk+1][1], pah[2], pal[2]);
            split2(c[2*kk+1][2], c[2*kk+1][3], pah[3], pal[3]);
#pragma unroll
            for (int nn = 0; nn < 4; nn++) {
                uint32_t off = 2u * (uint32_t)((kk * 16 + v_row) * ALDS + nn * 16 + v_col);
                uint32_t vh4[4], vl4[4];
                ldsm_x4_t(vh4, sbVh + off);
                ldsm_x4_t(vl4, sbVl + off);
                float* o0 = o[nn * 2 + 0];
                float* o1 = o[nn * 2 + 1];
                mma16816(o0, pah, &vh4[0]);
                mma16816(o1, pah, &vh4[2]);
                mma16816(o0, pah, &vl4[0]);
                mma16816(o1, pah, &vl4[2]);
                mma16816(o0, pal, &vh4[0]);
                mma16816(o1, pal, &vh4[2]);
            }
        }
    }

    // Epilogue: normalize, split, write [B,N,C] (C = h*64+d) as bf16 hi/lo
    float inv0 = 1.0f / l0, inv1 = 1.0f / l1;
    int n0r = qt * 128 + wid * 16 + (lane >> 2);
#pragma unroll
    for (int f = 0; f < 8; f++) {
        int colc = h * Dq + f * 8 + 2 * (lane & 3);
        size_t i0 = ((size_t)(b * Nq + n0r)) * Cq + colc;
        size_t i1 = ((size_t)(b * Nq + n0r + 8)) * Cq + colc;
        uint32_t hi, lo;
        split2(o[f][0] * inv0, o[f][1] * inv0, hi, lo);
        *(uint32_t*)&g_aoh[i0] = hi; *(uint32_t*)&g_aol[i0] = lo;
        split2(o[f][2] * inv1, o[f][3] * inv1, hi, lo);
        *(uint32_t*)&g_aoh[i1] = hi; *(uint32_t*)&g_aol[i1] = lo;
    }
}

// ---------------------------------------------------------------------------
extern "C" void kernel_launch(void* const* d_in, const int* in_sizes, int n_in,
                              void* d_out, int out_size) {
    const float* query     = (const float*)d_in[0];
    const float* mask      = (const float*)d_in[1];
    const float* W_qkv     = (const float*)d_in[2];
    const float* magnitude = (const float*)d_in[3];
    const float* W_loraA   = (const float*)d_in[4];
    const float* W_loraB   = (const float*)d_in[5];
    const float* W_proj    = (const float*)d_in[6];
    float* out = (float*)d_out;

    cudaFuncSetAttribute(mma_gemm_kernel<0>,
        cudaFuncAttributeMaxDynamicSharedMemorySize, SMEM_GEMM);
    cudaFuncSetAttribute(mma_gemm_kernel<1>,
        cudaFuncAttributeMaxDynamicSharedMemorySize, SMEM_GEMM);
    cudaFuncSetAttribute(attn_mma_kernel,
        cudaFuncAttributeMaxDynamicSharedMemorySize, SMEM_ATTN);

    __nv_bfloat16 *gAh, *gAl, *gBh, *gBl, *gaoh, *gaol;
    cudaGetSymbolAddress((void**)&gAh,  g_Ah);
    cudaGetSymbolAddress((void**)&gAl,  g_Al);
    cudaGetSymbolAddress((void**)&gBh,  g_Bh);
    cudaGetSymbolAddress((void**)&gBl,  g_Bl);
    cudaGetSymbolAddress((void**)&gaoh, g_aoh);
    cudaGetSymbolAddress((void**)&gaol, g_aol);

    // Stage 1: conversions + lora
    split_kernel<<<(Mq * Cq / 4) / 256, 256>>>(query, gAh, gAl);
    transpose_split_kernel<<<dim3(C3q / 32, Cq / 32), dim3(32, 8)>>>(W_qkv, gBh, gBl, Cq, C3q);
    wb2t_kernel<<<64, 256>>>(W_loraB, magnitude);
    lora_p_kernel<<<Mq, 256>>>(query, W_loraA);

    // Stage 2: qkv GEMM -> split-bf16 q/k/v (DoRA fused)
    mma_gemm_kernel<0><<<dim3(C3q / 128, Mq / 128), 256, SMEM_GEMM>>>(gAh, gAl, gBh, gBl, nullptr);

    // Stage 3: attention on tensor cores
    attn_mma_kernel<<<dim3(Hq, Nq / 128, Bq), 256, SMEM_ATTN>>>(mask);

    // Stage 4: proj GEMM (A = split attention output, no conversion pass)
    transpose_split_kernel<<<dim3(Cq / 32, Cq / 32), dim3(32, 8)>>>(W_proj, gBh, gBl, Cq, Cq);
    mma_gemm_kernel<1><<<dim3(Cq / 128, Mq / 128), 256, SMEM_GEMM>>>(gaoh, gaol, gBh, gBl, out);
}

// round 7
// speedup vs baseline: 2.7660x; 1.0987x over previous
#include <cuda_runtime.h>
#include <cuda_bf16.h>
#include <cstdint>
#include <math.h>

// Problem constants
#define Bq   4
#define Nq   2048
#define Cq   1024
#define Hq   16
#define Dq   64
#define Rq   16
#define Mq   (Bq*Nq)          // 8192 rows
#define C3q  (3*Cq)           // 3072
#define SCALEF 0.125f         // 1/sqrt(64)

// ---------------------------------------------------------------------------
// Device-global scratch (no cudaMalloc allowed)
// ---------------------------------------------------------------------------
__device__ __nv_bfloat16 g_qh[Mq*Cq], g_ql[Mq*Cq];    // q  [B,H,N,D] split
__device__ __nv_bfloat16 g_kh[Mq*Cq], g_kl[Mq*Cq];    // k
__device__ __nv_bfloat16 g_vh[Mq*Cq], g_vl[Mq*Cq];    // v
__device__ __nv_bfloat16 g_aoh[Mq*Cq], g_aol[Mq*Cq];  // attn out [B,N,C] split

__device__ __nv_bfloat16 g_Ah[Mq*Cq],  g_Al[Mq*Cq];    // qkv A split [M,K]
__device__ __nv_bfloat16 g_Bh[C3q*Cq], g_Bl[C3q*Cq];   // W^T split [N,K]

// ---------------------------------------------------------------------------
// helpers
// ---------------------------------------------------------------------------
__device__ __forceinline__ uint32_t smem_to_u32(const void* p) {
    uint32_t a;
    asm("{ .reg .u64 t; cvta.to.shared.u64 t, %1; cvt.u32.u64 %0, t; }"
        : "=r"(a) : "l"(p));
    return a;
}
__device__ __forceinline__ void ldsm_x4(uint32_t* r, uint32_t addr) {
    asm volatile("ldmatrix.sync.aligned.m8n8.x4.shared.b16 {%0,%1,%2,%3}, [%4];"
                 : "=r"(r[0]), "=r"(r[1]), "=r"(r[2]), "=r"(r[3]) : "r"(addr));
}
__device__ __forceinline__ void ldsm_x4_t(uint32_t* r, uint32_t addr) {
    asm volatile("ldmatrix.sync.aligned.m8n8.x4.trans.shared.b16 {%0,%1,%2,%3}, [%4];"
                 : "=r"(r[0]), "=r"(r[1]), "=r"(r[2]), "=r"(r[3]) : "r"(addr));
}
__device__ __forceinline__ void mma16816(float* c, const uint32_t* a, const uint32_t* b) {
    asm volatile("mma.sync.aligned.m16n8k16.row.col.f32.bf16.bf16.f32 "
        "{%0,%1,%2,%3}, {%4,%5,%6,%7}, {%8,%9}, {%0,%1,%2,%3};"
        : "+f"(c[0]), "+f"(c[1]), "+f"(c[2]), "+f"(c[3])
        : "r"(a[0]), "r"(a[1]), "r"(a[2]), "r"(a[3]), "r"(b[0]), "r"(b[1]));
}
__device__ __forceinline__ void split2(float x, float y, uint32_t& hi, uint32_t& lo) {
    __nv_bfloat16 hx = __float2bfloat16(x), hy = __float2bfloat16(y);
    __nv_bfloat16 lx = __float2bfloat16(x - __bfloat162float(hx));
    __nv_bfloat16 ly = __float2bfloat16(y - __bfloat162float(hy));
    __nv_bfloat162 H(hx, hy), L(lx, ly);
    hi = *(uint32_t*)&H; lo = *(uint32_t*)&L;
}
__device__ __forceinline__ void cp_async16(uint32_t dst, const void* src) {
    asm volatile("cp.async.cg.shared.global [%0], [%1], 16;"
                 :: "r"(dst), "l"(src) : "memory");
}
__device__ __forceinline__ void cp_commit() {
    asm volatile("cp.async.commit_group;" ::: "memory");
}
template<int N> __device__ __forceinline__ void cp_wait() {
    asm volatile("cp.async.wait_group %0;" :: "n"(N) : "memory");
}

// ---------------------------------------------------------------------------
// Conversion kernels
// ---------------------------------------------------------------------------
__global__ void split_kernel(const float* __restrict__ X,
                             __nv_bfloat16* __restrict__ H,
                             __nv_bfloat16* __restrict__ L) {
    int i = blockIdx.x * blockDim.x + threadIdx.x;
    float4 x = ((const float4*)X)[i];
    uint32_t h0, l0, h1, l1;
    split2(x.x, x.y, h0, l0);
    split2(x.z, x.w, h1, l1);
    ((uint32_t*)H)[2*i+0] = h0; ((uint32_t*)H)[2*i+1] = h1;
    ((uint32_t*)L)[2*i+0] = l0; ((uint32_t*)L)[2*i+1] = l1;
}

// generic W[K,N] -> [N,K] transpose + split (used for W_proj)
__global__ void transpose_split_kernel(const float* __restrict__ W,
                                       __nv_bfloat16* __restrict__ BH,
                                       __nv_bfloat16* __restrict__ BL,
                                       int K, int N) {
    __shared__ float tile[32][33];
    int n0 = blockIdx.x * 32, k0 = blockIdx.y * 32;
    int tx = threadIdx.x, ty = threadIdx.y;
#pragma unroll
    for (int i = 0; i < 4; i++)
        tile[ty + i * 8][tx] = W[(size_t)(k0 + ty + i * 8) * N + n0 + tx];
    __syncthreads();
#pragma unroll
    for (int i = 0; i < 4; i++) {
        int nl = ty + i * 8;
        float v = tile[tx][nl];
        __nv_bfloat16 h = __float2bfloat16(v);
        __nv_bfloat16 l = __float2bfloat16(v - __bfloat162float(h));
        size_t o = (size_t)(n0 + nl) * K + k0 + tx;
        BH[o] = h; BL[o] = l;
    }
}

// qkv weights: W_qkv[K,3C] -> [3C,K] transpose + split, with the LoRA/DoRA
// delta algebraically folded into the q columns:
//   Beff[:, n<C] += (W_loraA @ (mag .* W_loraB))[k][n]   (dot-16, fp32)
__global__ void transpose_split_qkv_kernel(const float* __restrict__ W,
                                           const float* __restrict__ WA,
                                           const float* __restrict__ WB,
                                           const float* __restrict__ mag,
                                           __nv_bfloat16* __restrict__ BH,
                                           __nv_bfloat16* __restrict__ BL) {
    __shared__ float tile[32][33];
    __shared__ float WAs[32][17];   // [k][r]
    __shared__ float WBs[16][33];   // [r][n] (mag applied)
    int n0 = blockIdx.x * 32, k0 = blockIdx.y * 32;
    int tx = threadIdx.x, ty = threadIdx.y;
    const bool doq = (n0 < Cq);
#pragma unroll
    for (int i = 0; i < 4; i++)
        tile[ty + i * 8][tx] = W[(size_t)(k0 + ty + i * 8) * C3q + n0 + tx];
    if (doq) {
        int fi = ty * 32 + tx;
#pragma unroll
        for (int i = 0; i < 2; i++) {
            int idx = fi + i * 256;             // 0..511
            int kr = idx >> 4, r = idx & 15;
            WAs[kr][r] = WA[(size_t)(k0 + kr) * Rq + r];
            int rr = idx >> 5, nn = idx & 31;
            WBs[rr][nn] = mag[(n0 + nn) >> 6] * WB[(size_t)rr * Cq + n0 + nn];
        }
    }
    __syncthreads();
#pragma unroll
    for (int i = 0; i < 4; i++) {
        int nl = ty + i * 8;
        float v = tile[tx][nl];
        if (doq) {
            float d = 0.f;
#pragma unroll
            for (int r = 0; r < Rq; r++) d += WAs[tx][r] * WBs[r][nl];
            v += d;
        }
        __nv_bfloat16 h = __float2bfloat16(v);
        __nv_bfloat16 l = __float2bfloat16(v - __bfloat162float(h));
        size_t o = (size_t)(n0 + nl) * Cq + k0 + tx;
        BH[o] = h; BL[o] = l;
    }
}

// ---------------------------------------------------------------------------
// mma.sync split-bf16 GEMM, cp.async 2-stage pipelined.
// 128x128 CTA tile, 8 warps (2m x 4n). MODE 0: qkv -> split q/k/v.
// MODE 1: proj -> fp32 out.
// ---------------------------------------------------------------------------
#define LDSS   72
#define TILEB  (128 * LDSS)
#define NKB    16
#define SMEM_GEMM (2 * 4 * TILEB * 2)      // 147456 B

template<int MODE>
__global__ __launch_bounds__(256, 1) void mma_gemm_kernel(
    const __nv_bfloat16* __restrict__ Ah, const __nv_bfloat16* __restrict__ Al,
    const __nv_bfloat16* __restrict__ Bh, const __nv_bfloat16* __restrict__ Bl,
    float* __restrict__ out)
{
    extern __shared__ __nv_bfloat16 smb[];
    const uint32_t sb = smem_to_u32(smb);

    const int bn = blockIdx.x * 128;
    const int bm = blockIdx.y * 128;
    const int t    = threadIdx.x;
    const int lane = t & 31;
    const int wid  = t >> 5;
    const int wm = wid & 1, wn = wid >> 1;

    const int a_row = lane & 15;
    const int a_col = (lane >> 4) << 3;
    const int b_row = (lane & 7) + ((lane & 16) ? 8 : 0);
    const int b_col = (lane & 8);

    auto load_stage = [&](int s, int kb) {
#pragma unroll
        for (int it = 0; it < 4; it++) {
            int idx = t + it * 256;
            int row = idx >> 3, ch = (idx & 7) * 8;
            size_t ga = (size_t)(bm + row) * Cq + kb * 64 + ch;
            size_t gb = (size_t)(bn + row) * Cq + kb * 64 + ch;
            uint32_t o = sb + (uint32_t)(s * 4 * TILEB + row * LDSS + ch) * 2;
            cp_async16(o + 0 * TILEB * 2, &Ah[ga]);
            cp_async16(o + 1 * TILEB * 2, &Al[ga]);
            cp_async16(o + 2 * TILEB * 2, &Bh[gb]);
            cp_async16(o + 3 * TILEB * 2, &Bl[gb]);
        }
        cp_commit();
    };

    float c[16][4];
#pragma unroll
    for (int i = 0; i < 16; i++)
#pragma unroll
        for (int j = 0; j < 4; j++) c[i][j] = 0.f;

    load_stage(0, 0);

    for (int kb = 0; kb < NKB; kb++) {
        const int s = kb & 1;
        if (kb + 1 < NKB) { load_stage(s ^ 1, kb + 1); cp_wait<1>(); }
        else              { cp_wait<0>(); }
        __syncthreads();

        const uint32_t sbAh = sb + (uint32_t)(s * 4 * TILEB) * 2;
        const uint32_t sbAl = sbAh + TILEB * 2;
        const uint32_t sbBh = sbAh + 2 * TILEB * 2;
        const uint32_t sbBl = sbAh + 3 * TILEB * 2;

#pragma unroll
        for (int k16 = 0; k16 < 4; k16++) {
            uint32_t ah[4][4], al[4][4];
#pragma unroll
            for (int fm = 0; fm < 4; fm++) {
                uint32_t off = 2u * (uint32_t)((wm * 64 + fm * 16 + a_row) * LDSS
                                               + k16 * 16 + a_col);
                ldsm_x4(ah[fm], sbAh + off);
                ldsm_x4(al[fm], sbAl + off);
            }
#pragma unroll
            for (int fn2 = 0; fn2 < 2; fn2++) {
                uint32_t off = 2u * (uint32_t)((wn * 32 + fn2 * 16 + b_row) * LDSS
                                               + k16 * 16 + b_col);
                uint32_t bh4[4], bl4[4];
                ldsm_x4(bh4, sbBh + off);
                ldsm_x4(bl4, sbBl + off);
#pragma unroll
                for (int fm = 0; fm < 4; fm++) {
                    float* c0 = c[fm * 4 + fn2 * 2 + 0];
                    float* c1 = c[fm * 4 + fn2 * 2 + 1];
                    mma16816(c0, ah[fm], &bh4[0]);
                    mma16816(c1, ah[fm], &bh4[2]);
                    mma16816(c0, ah[fm], &bl4[0]);
                    mma16816(c1, ah[fm], &bl4[2]);
                    mma16816(c0, al[fm], &bh4[0]);
                    mma16816(c1, al[fm], &bh4[2]);
                }
            }
        }
        __syncthreads();
    }

    // Epilogue
#pragma unroll
    for (int fm = 0; fm < 4; fm++) {
#pragma unroll
        for (int fn = 0; fn < 4; fn++) {
            const float* cc = c[fm * 4 + fn];
            int r0  = bm + wm * 64 + fm * 16 + (lane >> 2);
            int col = bn + wn * 32 + fn * 8 + (lane & 3) * 2;
#pragma unroll
            for (int half = 0; half < 2; half++) {
                int m = r0 + half * 8;
                float vx = cc[half * 2 + 0], vy = cc[half * 2 + 1];
                if (MODE == 1) {
                    *(float2*)(out + (size_t)m * Cq + col) = make_float2(vx, vy);
                } else {
                    int sel = col >> 10;
                    int within = col & (Cq - 1);
                    int h = within >> 6, d = within & 63;
                    int b = m >> 11, n = m & (Nq - 1);
                    size_t oidx = ((((size_t)b * Hq + h) * Nq) + n) * Dq + d;
                    uint32_t hi, lo;
                    split2(vx, vy, hi, lo);
                    __nv_bfloat16 *ph, *pl;
                    if (sel == 0)      { ph = g_qh; pl = g_ql; }
                    else if (sel == 1) { ph = g_kh; pl = g_kl; }
                    else               { ph = g_vh; pl = g_vl; }
                    *(uint32_t*)&ph[oidx] = hi;
                    *(uint32_t*)&pl[oidx] = lo;
                }
            }
        }
    }
}

// ---------------------------------------------------------------------------
// Flash attention on mma.sync, split-bf16, cp.async 2-stage K/V pipeline.
// Block = (h, qtile-128, b), 8 warps, warp w owns q rows w*16..w*16+15.
// ---------------------------------------------------------------------------
#define ALDS 72
#define KVB  (64 * ALDS)                       // bf16 elems per K/V buffer
#define SMEM_ATTN ((256 * ALDS + 2 * 4 * KVB) * 2)   // 110592 B

__global__ __launch_bounds__(256, 1) void attn_mma_kernel(const float* __restrict__ mask) {
    extern __shared__ __nv_bfloat16 sma[];
    __nv_bfloat16* Qh = sma;                    // [128][ALDS]
    __nv_bfloat16* Ql = sma + 128 * ALDS;
    const uint32_t sbQh = smem_to_u32(sma);
    const uint32_t sbQl = sbQh + 128 * ALDS * 2;
    const uint32_t sbKV = sbQh + 256 * ALDS * 2;

    const int h  = blockIdx.x, qt = blockIdx.y, b = blockIdx.z;
    const int t    = threadIdx.x;
    const int lane = t & 31;
    const int wid  = t >> 5;

    const size_t base = ((size_t)b * Hq + h) * Nq;

    auto load_kv = [&](int s, int kt) {
#pragma unroll
        for (int it = 0; it < 2; it++) {
            int idx = t + it * 256;              // 0..511
            int row = idx >> 3, ch = (idx & 7) * 8;
            size_t g = (base + (size_t)(kt * 64 + row)) * Dq + ch;
            uint32_t o = sbKV + (uint32_t)(s * 4 * KVB + row * ALDS + ch) * 2;
            cp_async16(o + 0 * KVB * 2, &g_kh[g]);
            cp_async16(o + 1 * KVB * 2, &g_kl[g]);
            cp_async16(o + 2 * KVB * 2, &g_vh[g]);
            cp_async16(o + 3 * KVB * 2, &g_vl[g]);
        }
        cp_commit();
    };

    // kick off KV stage 0 before the Q load for overlap
    load_kv(0, 0);

    const __nv_bfloat16* Qgh = g_qh + (base + (size_t)qt * 128) * Dq;
    const __nv_bfloat16* Qgl = g_ql + (base + (size_t)qt * 128) * Dq;
#pragma unroll
    for (int it = 0; it < 4; it++) {
        int idx = t + it * 256;
        int row = idx >> 3, ch = (idx & 7) * 8;
        *(uint4*)&Qh[row * ALDS + ch] = *(const uint4*)&Qgh[row * Dq + ch];
        *(uint4*)&Ql[row * ALDS + ch] = *(const uint4*)&Qgl[row * Dq + ch];
    }
    __syncthreads();

    const int a_row = lane & 15;
    const int a_col = (lane >> 4) << 3;
    uint32_t aQh[4][4], aQl[4][4];
#pragma unroll
    for (int kk = 0; kk < 4; kk++) {
        uint32_t off = 2u * (uint32_t)((wid * 16 + a_row) * ALDS + kk * 16 + a_col);
        ldsm_x4(aQh[kk], sbQh + off);
        ldsm_x4(aQl[kk], sbQl + off);
    }

    const int b_row = (lane & 7) + ((lane & 16) ? 8 : 0);
    const int b_col = (lane & 8);
    const int v_row = lane & 15;
    const int v_col = (lane & 16) ? 8 : 0;

    float o[8][4];
#pragma unroll
    for (int i = 0; i < 8; i++)
#pragma unroll
        for (int j = 0; j < 4; j++) o[i][j] = 0.f;
    float m0 = -1e30f, m1 = -1e30f, l0 = 0.f, l1 = 0.f;

    const float* maskrow = mask + (size_t)b * Nq * Nq
                         + (size_t)(qt * 128 + wid * 16 + (lane >> 2)) * Nq;

    for (int kt = 0; kt < Nq / 64; kt++) {
        const int s = kt & 1;
        if (kt + 1 < Nq / 64) { load_kv(s ^ 1, kt + 1); cp_wait<1>(); }
        else                  { cp_wait<0>(); }
        __syncthreads();

        const uint32_t sbKh = sbKV + (uint32_t)(s * 4 * KVB) * 2;
        const uint32_t sbKl = sbKh + KVB * 2;
        const uint32_t sbVh = sbKh + 2 * KVB * 2;
        const uint32_t sbVl = sbKh + 3 * KVB * 2;

        // S = Q K^T (16 x 64 per warp), 3-term split
        float c[8][4];
#pragma unroll
        for (int i = 0; i < 8; i++)
#pragma unroll
            for (int j = 0; j < 4; j++) c[i][j] = 0.f;
#pragma unroll
        for (int fn2 = 0; fn2 < 4; fn2++) {
#pragma unroll
            for (int kk = 0; kk < 4; kk++) {
                uint32_t off = 2u * (uint32_t)((fn2 * 16 + b_row) * ALDS + kk * 16 + b_col);
                uint32_t bh4[4], bl4[4];
                ldsm_x4(bh4, sbKh + off);
                ldsm_x4(bl4, sbKl + off);
                float* c0 = c[fn2 * 2 + 0];
                float* c1 = c[fn2 * 2 + 1];
                mma16816(c0, aQh[kk], &bh4[0]);
                mma16816(c1, aQh[kk], &bh4[2]);
                mma16816(c0, aQh[kk], &bl4[0]);
                mma16816(c1, aQh[kk], &bl4[2]);
                mma16816(c0, aQl[kk], &bh4[0]);
                mma16816(c1, aQl[kk], &bh4[2]);
            }
        }

        // scale + mask
        const int colbase = kt * 64 + 2 * (lane & 3);
#pragma unroll
        for (int f = 0; f < 8; f++) {
            float2 mk0 = *(const float2*)&maskrow[colbase + f * 8];
            float2 mk1 = *(const float2*)&maskrow[8 * Nq + colbase + f * 8];
            c[f][0] = c[f][0] * SCALEF + mk0.x;
            c[f][1] = c[f][1] * SCALEF + mk0.y;
            c[f][2] = c[f][2] * SCALEF + mk1.x;
            c[f][3] = c[f][3] * SCALEF + mk1.y;
        }

        // online softmax
        float rm0 = -1e30f, rm1 = -1e30f;
#pragma unroll
        for (int f = 0; f < 8; f++) {
            rm0 = fmaxf(rm0, fmaxf(c[f][0], c[f][1]));
            rm1 = fmaxf(rm1, fmaxf(c[f][2], c[f][3]));
        }
        rm0 = fmaxf(rm0, __shfl_xor_sync(0xffffffffu, rm0, 1));
        rm0 = fmaxf(rm0, __shfl_xor_sync(0xffffffffu, rm0, 2));
        rm1 = fmaxf(rm1, __shfl_xor_sync(0xffffffffu, rm1, 1));
        rm1 = fmaxf(rm1, __shfl_xor_sync(0xffffffffu, rm1, 2));
        float nm0 = fmaxf(m0, rm0), nm1 = fmaxf(m1, rm1);
        float sc0 = __expf(m0 - nm0), sc1 = __expf(m1 - nm1);
        float s0 = 0.f, s1 = 0.f;
#pragma unroll
        for (int f = 0; f < 8; f++) {
            c[f][0] = __expf(c[f][0] - nm0);
            c[f][1] = __expf(c[f][1] - nm0);
            c[f][2] = __expf(c[f][2] - nm1);
            c[f][3] = __expf(c[f][3] - nm1);
            s0 += c[f][0] + c[f][1];
            s1 += c[f][2] + c[f][3];
        }
        s0 += __shfl_xor_sync(0xffffffffu, s0, 1);
        s0 += __shfl_xor_sync(0xffffffffu, s0, 2);
        s1 += __shfl_xor_sync(0xffffffffu, s1, 1);
        s1 += __shfl_xor_sync(0xffffffffu, s1, 2);
        l0 = l0 * sc0 + s0; m0 = nm0;
        l1 = l1 * sc1 + s1; m1 = nm1;
#pragma unroll
        for (int f = 0; f < 8; f++) {
            o[f][0] *= sc0; o[f][1] *= sc0;
            o[f][2] *= sc1; o[f][3] *= sc1;
        }

        // O += P V (P repacked C->A in registers, split)
#pragma unroll
        for (int kk = 0; kk < 4; kk++) {
            uint32_t pah[4], pal[4];
            split2(c[2*kk  ][0], c[2*kk  ][1], pah[0], pal[0]);
            split2(c[2*kk  ][2], c[2*kk  ][3], pah[1], pal[1]);
            split2(c[2*kk+1][0], c[2*kk+1][1], pah[2], pal[2]);
            split2(c[2*kk+1][2], c[2*kk+1][3], pah[3], pal[3]);
#pragma unroll
            for (int nn = 0; nn < 4; nn++) {
                uint32_t off = 2u * (uint32_t)((kk * 16 + v_row) * ALDS + nn * 16 + v_col);
                uint32_t vh4[4], vl4[4];
                ldsm_x4_t(vh4, sbVh + off);
                ldsm_x4_t(vl4, sbVl + off);
                float* o0 = o[nn * 2 + 0];
                float* o1 = o[nn * 2 + 1];
                mma16816(o0, pah, &vh4[0]);
                mma16816(o1, pah, &vh4[2]);
                mma16816(o0, pah, &vl4[0]);
                mma16816(o1, pah, &vl4[2]);
                mma16816(o0, pal, &vh4[0]);
                mma16816(o1, pal, &vh4[2]);
            }
        }
        __syncthreads();
    }

    // Epilogue
    float inv0 = 1.0f / l0, inv1 = 1.0f / l1;
    int n0r = qt * 128 + wid * 16 + (lane >> 2);
#pragma unroll
    for (int f = 0; f < 8; f++) {
        int colc = h * Dq + f * 8 + 2 * (lane & 3);
        size_t i0 = ((size_t)(b * Nq + n0r)) * Cq + colc;
        size_t i1 = ((size_t)(b * Nq + n0r + 8)) * Cq + colc;
        uint32_t hi, lo;
        split2(o[f][0] * inv0, o[f][1] * inv0, hi, lo);
        *(uint32_t*)&g_aoh[i0] = hi; *(uint32_t*)&g_aol[i0] = lo;
        split2(o[f][2] * inv1, o[f][3] * inv1, hi, lo);
        *(uint32_t*)&g_aoh[i1] = hi; *(uint32_t*)&g_aol[i1] = lo;
    }
}

// ---------------------------------------------------------------------------
extern "C" void kernel_launch(void* const* d_in, const int* in_sizes, int n_in,
                              void* d_out, int out_size) {
    const float* query     = (const float*)d_in[0];
    const float* mask      = (const float*)d_in[1];
    const float* W_qkv     = (const float*)d_in[2];
    const float* magnitude = (const float*)d_in[3];
    const float* W_loraA   = (const float*)d_in[4];
    const float* W_loraB   = (const float*)d_in[5];
    const float* W_proj    = (const float*)d_in[6];
    float* out = (float*)d_out;

    cudaFuncSetAttribute(mma_gemm_kernel<0>,
        cudaFuncAttributeMaxDynamicSharedMemorySize, SMEM_GEMM);
    cudaFuncSetAttribute(mma_gemm_kernel<1>,
        cudaFuncAttributeMaxDynamicSharedMemorySize, SMEM_GEMM);
    cudaFuncSetAttribute(attn_mma_kernel,
        cudaFuncAttributeMaxDynamicSharedMemorySize, SMEM_ATTN);

    __nv_bfloat16 *gAh, *gAl, *gBh, *gBl, *gaoh, *gaol;
    cudaGetSymbolAddress((void**)&gAh,  g_Ah);
    cudaGetSymbolAddress((void**)&gAl,  g_Al);
    cudaGetSymbolAddress((void**)&gBh,  g_Bh);
    cudaGetSymbolAddress((void**)&gBl,  g_Bl);
    cudaGetSymbolAddress((void**)&gaoh, g_aoh);
    cudaGetSymbolAddress((void**)&gaol, g_aol);

    // Stage 1: conversions (LoRA folded into qkv weights algebraically)
    split_kernel<<<(Mq * Cq / 4) / 256, 256>>>(query, gAh, gAl);
    transpose_split_qkv_kernel<<<dim3(C3q / 32, Cq / 32), dim3(32, 8)>>>(
        W_qkv, W_loraA, W_loraB, magnitude, gBh, gBl);

    // Stage 2: qkv GEMM -> split-bf16 q/k/v
    mma_gemm_kernel<0><<<dim3(C3q / 128, Mq / 128), 256, SMEM_GEMM>>>(gAh, gAl, gBh, gBl, nullptr);

    // Stage 3: attention on tensor cores (pipelined)
    attn_mma_kernel<<<dim3(Hq, Nq / 128, Bq), 256, SMEM_ATTN>>>(mask);

    // Stage 4: proj GEMM
    transpose_split_kernel<<<dim3(Cq / 32, Cq / 32), dim3(32, 8)>>>(W_proj, gBh, gBl, Cq, Cq);
    mma_gemm_kernel<1><<<dim3(Cq / 128, Mq / 128), 256, SMEM_GEMM>>>(gaoh, gaol, gBh, gBl, out);
}

// round 8
// speedup vs baseline: 2.9312x; 1.0597x over previous
#include <cuda_runtime.h>
#include <cuda_bf16.h>
#include <cstdint>
#include <math.h>

// Problem constants
#define Bq   4
#define Nq   2048
#define Cq   1024
#define Hq   16
#define Dq   64
#define Rq   16
#define Mq   (Bq*Nq)          // 8192 rows
#define C3q  (3*Cq)           // 3072
#define SCALEF 0.125f         // 1/sqrt(64)

// ---------------------------------------------------------------------------
// Device-global scratch
// ---------------------------------------------------------------------------
__device__ __nv_bfloat16 g_qh[Mq*Cq], g_ql[Mq*Cq];    // q  [B,H,N,D] split
__device__ __nv_bfloat16 g_kh[Mq*Cq], g_kl[Mq*Cq];    // k
__device__ __nv_bfloat16 g_vh[Mq*Cq], g_vl[Mq*Cq];    // v
__device__ __nv_bfloat16 g_aoh[Mq*Cq], g_aol[Mq*Cq];  // attn out [B,N,C] split

__device__ __nv_bfloat16 g_Ah[Mq*Cq],  g_Al[Mq*Cq];    // qkv A split [M,K]
__device__ __nv_bfloat16 g_Bh[C3q*Cq], g_Bl[C3q*Cq];   // W^T split [N,K]

// ---------------------------------------------------------------------------
// helpers
// ---------------------------------------------------------------------------
__device__ __forceinline__ uint32_t smem_to_u32(const void* p) {
    uint32_t a;
    asm("{ .reg .u64 t; cvta.to.shared.u64 t, %1; cvt.u32.u64 %0, t; }"
        : "=r"(a) : "l"(p));
    return a;
}
__device__ __forceinline__ void ldsm_x4(uint32_t* r, uint32_t addr) {
    asm volatile("ldmatrix.sync.aligned.m8n8.x4.shared.b16 {%0,%1,%2,%3}, [%4];"
                 : "=r"(r[0]), "=r"(r[1]), "=r"(r[2]), "=r"(r[3]) : "r"(addr));
}
__device__ __forceinline__ void ldsm_x4_t(uint32_t* r, uint32_t addr) {
    asm volatile("ldmatrix.sync.aligned.m8n8.x4.trans.shared.b16 {%0,%1,%2,%3}, [%4];"
                 : "=r"(r[0]), "=r"(r[1]), "=r"(r[2]), "=r"(r[3]) : "r"(addr));
}
__device__ __forceinline__ void mma16816(float* c, const uint32_t* a, const uint32_t* b) {
    asm volatile("mma.sync.aligned.m16n8k16.row.col.f32.bf16.bf16.f32 "
        "{%0,%1,%2,%3}, {%4,%5,%6,%7}, {%8,%9}, {%0,%1,%2,%3};"
        : "+f"(c[0]), "+f"(c[1]), "+f"(c[2]), "+f"(c[3])
        : "r"(a[0]), "r"(a[1]), "r"(a[2]), "r"(a[3]), "r"(b[0]), "r"(b[1]));
}
__device__ __forceinline__ void split2(float x, float y, uint32_t& hi, uint32_t& lo) {
    __nv_bfloat16 hx = __float2bfloat16(x), hy = __float2bfloat16(y);
    __nv_bfloat16 lx = __float2bfloat16(x - __bfloat162float(hx));
    __nv_bfloat16 ly = __float2bfloat16(y - __bfloat162float(hy));
    __nv_bfloat162 H(hx, hy), L(lx, ly);
    hi = *(uint32_t*)&H; lo = *(uint32_t*)&L;
}
__device__ __forceinline__ void cp_async16(uint32_t dst, const void* src) {
    asm volatile("cp.async.cg.shared.global [%0], [%1], 16;"
                 :: "r"(dst), "l"(src) : "memory");
}
__device__ __forceinline__ void cp_commit() {
    asm volatile("cp.async.commit_group;" ::: "memory");
}
template<int N> __device__ __forceinline__ void cp_wait() {
    asm volatile("cp.async.wait_group %0;" :: "n"(N) : "memory");
}

// ---------------------------------------------------------------------------
// Conversion kernels
// ---------------------------------------------------------------------------
__global__ void split_kernel(const float* __restrict__ X,
                             __nv_bfloat16* __restrict__ H,
                             __nv_bfloat16* __restrict__ L) {
    int i = blockIdx.x * blockDim.x + threadIdx.x;
    float4 x = ((const float4*)X)[i];
    uint32_t h0, l0, h1, l1;
    split2(x.x, x.y, h0, l0);
    split2(x.z, x.w, h1, l1);
    ((uint32_t*)H)[2*i+0] = h0; ((uint32_t*)H)[2*i+1] = h1;
    ((uint32_t*)L)[2*i+0] = l0; ((uint32_t*)L)[2*i+1] = l1;
}

__global__ void transpose_split_kernel(const float* __restrict__ W,
                                       __nv_bfloat16* __restrict__ BH,
                                       __nv_bfloat16* __restrict__ BL,
                                       int K, int N) {
    __shared__ float tile[32][33];
    int n0 = blockIdx.x * 32, k0 = blockIdx.y * 32;
    int tx = threadIdx.x, ty = threadIdx.y;
#pragma unroll
    for (int i = 0; i < 4; i++)
        tile[ty + i * 8][tx] = W[(size_t)(k0 + ty + i * 8) * N + n0 + tx];
    __syncthreads();
#pragma unroll
    for (int i = 0; i < 4; i++) {
        int nl = ty + i * 8;
        float v = tile[tx][nl];
        __nv_bfloat16 h = __float2bfloat16(v);
        __nv_bfloat16 l = __float2bfloat16(v - __bfloat162float(h));
        size_t o = (size_t)(n0 + nl) * K + k0 + tx;
        BH[o] = h; BL[o] = l;
    }
}

// W_qkv[K,3C] -> [3C,K] transpose + split with LoRA delta folded into q cols
__global__ void transpose_split_qkv_kernel(const float* __restrict__ W,
                                           const float* __restrict__ WA,
                                           const float* __restrict__ WB,
                                           const float* __restrict__ mag,
                                           __nv_bfloat16* __restrict__ BH,
                                           __nv_bfloat16* __restrict__ BL) {
    __shared__ float tile[32][33];
    __shared__ float WAs[32][17];   // [k][r]
    __shared__ float WBs[16][33];   // [r][n] (mag applied)
    int n0 = blockIdx.x * 32, k0 = blockIdx.y * 32;
    int tx = threadIdx.x, ty = threadIdx.y;
    const bool doq = (n0 < Cq);
#pragma unroll
    for (int i = 0; i < 4; i++)
        tile[ty + i * 8][tx] = W[(size_t)(k0 + ty + i * 8) * C3q + n0 + tx];
    if (doq) {
        int fi = ty * 32 + tx;
#pragma unroll
        for (int i = 0; i < 2; i++) {
            int idx = fi + i * 256;
            int kr = idx >> 4, r = idx & 15;
            WAs[kr][r] = WA[(size_t)(k0 + kr) * Rq + r];
            int rr = idx >> 5, nn = idx & 31;
            WBs[rr][nn] = mag[(n0 + nn) >> 6] * WB[(size_t)rr * Cq + n0 + nn];
        }
    }
    __syncthreads();
#pragma unroll
    for (int i = 0; i < 4; i++) {
        int nl = ty + i * 8;
        float v = tile[tx][nl];
        if (doq) {
            float d = 0.f;
#pragma unroll
            for (int r = 0; r < Rq; r++) d += WAs[tx][r] * WBs[r][nl];
            v += d;
        }
        __nv_bfloat16 h = __float2bfloat16(v);
        __nv_bfloat16 l = __float2bfloat16(v - __bfloat162float(h));
        size_t o = (size_t)(n0 + nl) * Cq + k0 + tx;
        BH[o] = h; BL[o] = l;
    }
}

// ---------------------------------------------------------------------------
// mma.sync split-bf16 GEMM, cp.async 3-stage pipelined.
// ---------------------------------------------------------------------------
#define LDSS   72
#define TILEB  (128 * LDSS)
#define NKB    16
#define NST    3
#define SMEM_GEMM (NST * 4 * TILEB * 2)     // 221184 B

template<int MODE>
__global__ __launch_bounds__(256, 1) void mma_gemm_kernel(
    const __nv_bfloat16* __restrict__ Ah, const __nv_bfloat16* __restrict__ Al,
    const __nv_bfloat16* __restrict__ Bh, const __nv_bfloat16* __restrict__ Bl,
    float* __restrict__ out)
{
    extern __shared__ __nv_bfloat16 smb[];
    const uint32_t sb = smem_to_u32(smb);

    const int bn = blockIdx.x * 128;
    const int bm = blockIdx.y * 128;
    const int t    = threadIdx.x;
    const int lane = t & 31;
    const int wid  = t >> 5;
    const int wm = wid & 1, wn = wid >> 1;

    const int a_row = lane & 15;
    const int a_col = (lane >> 4) << 3;
    const int b_row = (lane & 7) + ((lane & 16) ? 8 : 0);
    const int b_col = (lane & 8);

    auto load_stage = [&](int s, int kb) {
#pragma unroll
        for (int it = 0; it < 4; it++) {
            int idx = t + it * 256;
            int row = idx >> 3, ch = (idx & 7) * 8;
            size_t ga = (size_t)(bm + row) * Cq + kb * 64 + ch;
            size_t gb = (size_t)(bn + row) * Cq + kb * 64 + ch;
            uint32_t o = sb + (uint32_t)(s * 4 * TILEB + row * LDSS + ch) * 2;
            cp_async16(o + 0 * TILEB * 2, &Ah[ga]);
            cp_async16(o + 1 * TILEB * 2, &Al[ga]);
            cp_async16(o + 2 * TILEB * 2, &Bh[gb]);
            cp_async16(o + 3 * TILEB * 2, &Bl[gb]);
        }
        cp_commit();
    };

    float c[16][4];
#pragma unroll
    for (int i = 0; i < 16; i++)
#pragma unroll
        for (int j = 0; j < 4; j++) c[i][j] = 0.f;

    load_stage(0, 0);
    load_stage(1, 1);

    int s = 0;
    for (int kb = 0; kb < NKB; kb++) {
        if (kb + 2 < NKB) {
            int s2 = s + 2; if (s2 >= NST) s2 -= NST;
            load_stage(s2, kb + 2);
            cp_wait<2>();
        } else if (kb + 1 < NKB) {
            cp_wait<1>();
        } else {
            cp_wait<0>();
        }
        __syncthreads();

        const uint32_t sbAh = sb + (uint32_t)(s * 4 * TILEB) * 2;
        const uint32_t sbAl = sbAh + TILEB * 2;
        const uint32_t sbBh = sbAh + 2 * TILEB * 2;
        const uint32_t sbBl = sbAh + 3 * TILEB * 2;

#pragma unroll
        for (int k16 = 0; k16 < 4; k16++) {
            uint32_t ah[4][4], al[4][4];
#pragma unroll
            for (int fm = 0; fm < 4; fm++) {
                uint32_t off = 2u * (uint32_t)((wm * 64 + fm * 16 + a_row) * LDSS
                                               + k16 * 16 + a_col);
                ldsm_x4(ah[fm], sbAh + off);
                ldsm_x4(al[fm], sbAl + off);
            }
#pragma unroll
            for (int fn2 = 0; fn2 < 2; fn2++) {
                uint32_t off = 2u * (uint32_t)((wn * 32 + fn2 * 16 + b_row) * LDSS
                                               + k16 * 16 + b_col);
                uint32_t bh4[4], bl4[4];
                ldsm_x4(bh4, sbBh + off);
                ldsm_x4(bl4, sbBl + off);
#pragma unroll
                for (int fm = 0; fm < 4; fm++) {
                    float* c0 = c[fm * 4 + fn2 * 2 + 0];
                    float* c1 = c[fm * 4 + fn2 * 2 + 1];
                    mma16816(c0, ah[fm], &bh4[0]);
                    mma16816(c1, ah[fm], &bh4[2]);
                    mma16816(c0, ah[fm], &bl4[0]);
                    mma16816(c1, ah[fm], &bl4[2]);
                    mma16816(c0, al[fm], &bh4[0]);
                    mma16816(c1, al[fm], &bh4[2]);
                }
            }
        }
        __syncthreads();
        if (++s == NST) s = 0;
    }

    // Epilogue
#pragma unroll
    for (int fm = 0; fm < 4; fm++) {
#pragma unroll
        for (int fn = 0; fn < 4; fn++) {
            const float* cc = c[fm * 4 + fn];
            int r0  = bm + wm * 64 + fm * 16 + (lane >> 2);
            int col = bn + wn * 32 + fn * 8 + (lane & 3) * 2;
#pragma unroll
            for (int half = 0; half < 2; half++) {
                int m = r0 + half * 8;
                float vx = cc[half * 2 + 0], vy = cc[half * 2 + 1];
                if (MODE == 1) {
                    *(float2*)(out + (size_t)m * Cq + col) = make_float2(vx, vy);
                } else {
                    int sel = col >> 10;
                    int within = col & (Cq - 1);
                    int h = within >> 6, d = within & 63;
                    int b = m >> 11, n = m & (Nq - 1);
                    size_t oidx = ((((size_t)b * Hq + h) * Nq) + n) * Dq + d;
                    uint32_t hi, lo;
                    split2(vx, vy, hi, lo);
                    __nv_bfloat16 *ph, *pl;
                    if (sel == 0)      { ph = g_qh; pl = g_ql; }
                    else if (sel == 1) { ph = g_kh; pl = g_kl; }
                    else               { ph = g_vh; pl = g_vl; }
                    *(uint32_t*)&ph[oidx] = hi;
                    *(uint32_t*)&pl[oidx] = lo;
                }
            }
        }
    }
}

// ---------------------------------------------------------------------------
// Flash attention on mma.sync, split-bf16. cp.async 2-stage pipeline now
// carries K/V AND the mask tile (mask gmem latency hidden under MMAs).
// Block = (h, qtile-128, b), 8 warps, warp w owns q rows w*16..w*16+15.
// ---------------------------------------------------------------------------
#define ALDS 72
#define KVB  (64 * ALDS)                         // bf16 elems per K/V buffer
#define Q_BYTES   (256 * ALDS * 2)               // 36864
#define KV_BYTES  (2 * 4 * KVB * 2)              // 73728
#define MSK_OFF   (Q_BYTES + KV_BYTES)           // 110592
#define MSK_STRIDE 68                            // floats per mask row (16B-aligned)
#define MSK_STAGE (128 * MSK_STRIDE * 4)         // 34816 B
#define SMEM_ATTN (MSK_OFF + 2 * MSK_STAGE)      // 180224 B

__global__ __launch_bounds__(256, 1) void attn_mma_kernel(const float* __restrict__ mask) {
    extern __shared__ __nv_bfloat16 sma[];
    __nv_bfloat16* Qh = sma;                    // [128][ALDS]
    __nv_bfloat16* Ql = sma + 128 * ALDS;
    char* smc = (char*)sma;
    const uint32_t sbQh = smem_to_u32(sma);
    const uint32_t sbQl = sbQh + 128 * ALDS * 2;
    const uint32_t sbKV = sbQh + Q_BYTES;
    const uint32_t sbMsk = sbQh + MSK_OFF;

    const int h  = blockIdx.x, qt = blockIdx.y, b = blockIdx.z;
    const int t    = threadIdx.x;
    const int lane = t & 31;
    const int wid  = t >> 5;

    const size_t base = ((size_t)b * Hq + h) * Nq;
    const float* maskbase = mask + (size_t)b * Nq * Nq + (size_t)(qt * 128) * Nq;

    auto load_stage = [&](int s, int kt) {
        // K/V split tiles (64 x 64 bf16 x4 buffers)
#pragma unroll
        for (int it = 0; it < 2; it++) {
            int idx = t + it * 256;              // 0..511
            int row = idx >> 3, ch = (idx & 7) * 8;
            size_t g = (base + (size_t)(kt * 64 + row)) * Dq + ch;
            uint32_t o = sbKV + (uint32_t)(s * 4 * KVB + row * ALDS + ch) * 2;
            cp_async16(o + 0 * KVB * 2, &g_kh[g]);
            cp_async16(o + 1 * KVB * 2, &g_kl[g]);
            cp_async16(o + 2 * KVB * 2, &g_vh[g]);
            cp_async16(o + 3 * KVB * 2, &g_vl[g]);
        }
        // mask tile (128 rows x 64 fp32)
#pragma unroll
        for (int it = 0; it < 8; it++) {
            int idx = t + it * 256;              // 0..2047
            int row = idx >> 4, chunk = idx & 15;
            const float* src = maskbase + (size_t)row * Nq + kt * 64 + chunk * 4;
            uint32_t dst = sbMsk + (uint32_t)(s * MSK_STAGE + row * (MSK_STRIDE * 4) + chunk * 16);
            cp_async16(dst, src);
        }
        cp_commit();
    };

    load_stage(0, 0);

    const __nv_bfloat16* Qgh = g_qh + (base + (size_t)qt * 128) * Dq;
    const __nv_bfloat16* Qgl = g_ql + (base + (size_t)qt * 128) * Dq;
#pragma unroll
    for (int it = 0; it < 4; it++) {
        int idx = t + it * 256;
        int row = idx >> 3, ch = (idx & 7) * 8;
        *(uint4*)&Qh[row * ALDS + ch] = *(const uint4*)&Qgh[row * Dq + ch];
        *(uint4*)&Ql[row * ALDS + ch] = *(const uint4*)&Qgl[row * Dq + ch];
    }
    __syncthreads();

    const int a_row = lane & 15;
    const int a_col = (lane >> 4) << 3;
    uint32_t aQh[4][4], aQl[4][4];
#pragma unroll
    for (int kk = 0; kk < 4; kk++) {
        uint32_t off = 2u * (uint32_t)((wid * 16 + a_row) * ALDS + kk * 16 + a_col);
        ldsm_x4(aQh[kk], sbQh + off);
        ldsm_x4(aQl[kk], sbQl + off);
    }

    const int b_row = (lane & 7) + ((lane & 16) ? 8 : 0);
    const int b_col = (lane & 8);
    const int v_row = lane & 15;
    const int v_col = (lane & 16) ? 8 : 0;

    float o[8][4];
#pragma unroll
    for (int i = 0; i < 8; i++)
#pragma unroll
        for (int j = 0; j < 4; j++) o[i][j] = 0.f;
    float m0 = -1e30f, m1 = -1e30f, l0 = 0.f, l1 = 0.f;

    const int rloc0 = wid * 16 + (lane >> 2);     // mask smem row (first half)
    const int mcol  = 2 * (lane & 3);

    for (int kt = 0; kt < Nq / 64; kt++) {
        const int s = kt & 1;
        if (kt + 1 < Nq / 64) { load_stage(s ^ 1, kt + 1); cp_wait<1>(); }
        else                  { cp_wait<0>(); }
        __syncthreads();

        const uint32_t sbKh = sbKV + (uint32_t)(s * 4 * KVB) * 2;
        const uint32_t sbKl = sbKh + KVB * 2;
        const uint32_t sbVh = sbKh + 2 * KVB * 2;
        const uint32_t sbVl = sbKh + 3 * KVB * 2;
        const float* mskS = (const float*)(smc + MSK_OFF + s * MSK_STAGE);

        // S = Q K^T (16 x 64 per warp), 3-term split
        float c[8][4];
#pragma unroll
        for (int i = 0; i < 8; i++)
#pragma unroll
            for (int j = 0; j < 4; j++) c[i][j] = 0.f;
#pragma unroll
        for (int fn2 = 0; fn2 < 4; fn2++) {
#pragma unroll
            for (int kk = 0; kk < 4; kk++) {
                uint32_t off = 2u * (uint32_t)((fn2 * 16 + b_row) * ALDS + kk * 16 + b_col);
                uint32_t bh4[4], bl4[4];
                ldsm_x4(bh4, sbKh + off);
                ldsm_x4(bl4, sbKl + off);
                float* c0 = c[fn2 * 2 + 0];
                float* c1 = c[fn2 * 2 + 1];
                mma16816(c0, aQh[kk], &bh4[0]);
                mma16816(c1, aQh[kk], &bh4[2]);
                mma16816(c0, aQh[kk], &bl4[0]);
                mma16816(c1, aQh[kk], &bl4[2]);
                mma16816(c0, aQl[kk], &bh4[0]);
                mma16816(c1, aQl[kk], &bh4[2]);
            }
        }

        // scale + mask (from smem)
#pragma unroll
        for (int f = 0; f < 8; f++) {
            float2 mk0 = *(const float2*)&mskS[(rloc0    ) * MSK_STRIDE + f * 8 + mcol];
            float2 mk1 = *(const float2*)&mskS[(rloc0 + 8) * MSK_STRIDE + f * 8 + mcol];
            c[f][0] = c[f][0] * SCALEF + mk0.x;
            c[f][1] = c[f][1] * SCALEF + mk0.y;
            c[f][2] = c[f][2] * SCALEF + mk1.x;
            c[f][3] = c[f][3] * SCALEF + mk1.y;
        }

        // online softmax
        float rm0 = -1e30f, rm1 = -1e30f;
#pragma unroll
        for (int f = 0; f < 8; f++) {
            rm0 = fmaxf(rm0, fmaxf(c[f][0], c[f][1]));
            rm1 = fmaxf(rm1, fmaxf(c[f][2], c[f][3]));
        }
        rm0 = fmaxf(rm0, __shfl_xor_sync(0xffffffffu, rm0, 1));
        rm0 = fmaxf(rm0, __shfl_xor_sync(0xffffffffu, rm0, 2));
        rm1 = fmaxf(rm1, __shfl_xor_sync(0xffffffffu, rm1, 1));
        rm1 = fmaxf(rm1, __shfl_xor_sync(0xffffffffu, rm1, 2));
        float nm0 = fmaxf(m0, rm0), nm1 = fmaxf(m1, rm1);
        float sc0 = __expf(m0 - nm0), sc1 = __expf(m1 - nm1);
        float s0 = 0.f, s1 = 0.f;
#pragma unroll
        for (int f = 0; f < 8; f++) {
            c[f][0] = __expf(c[f][0] - nm0);
            c[f][1] = __expf(c[f][1] - nm0);
            c[f][2] = __expf(c[f][2] - nm1);
            c[f][3] = __expf(c[f][3] - nm1);
            s0 += c[f][0] + c[f][1];
            s1 += c[f][2] + c[f][3];
        }
        s0 += __shfl_xor_sync(0xffffffffu, s0, 1);
        s0 += __shfl_xor_sync(0xffffffffu, s0, 2);
        s1 += __shfl_xor_sync(0xffffffffu, s1, 1);
        s1 += __shfl_xor_sync(0xffffffffu, s1, 2);
        l0 = l0 * sc0 + s0; m0 = nm0;
        l1 = l1 * sc1 + s1; m1 = nm1;
#pragma unroll
        for (int f = 0; f < 8; f++) {
            o[f][0] *= sc0; o[f][1] *= sc0;
            o[f][2] *= sc1; o[f][3] *= sc1;
        }

        // O += P V
#pragma unroll
        for (int kk = 0; kk < 4; kk++) {
            uint32_t pah[4], pal[4];
            split2(c[2*kk  ][0], c[2*kk  ][1], pah[0], pal[0]);
            split2(c[2*kk  ][2], c[2*kk  ][3], pah[1], pal[1]);
            split2(c[2*kk+1][0], c[2*kk+1][1], pah[2], pal[2]);
            split2(c[2*kk+1][2], c[2*kk+1][3], pah[3], pal[3]);
#pragma unroll
            for (int nn = 0; nn < 4; nn++) {
                uint32_t off = 2u * (uint32_t)((kk * 16 + v_row) * ALDS + nn * 16 + v_col);
                uint32_t vh4[4], vl4[4];
                ldsm_x4_t(vh4, sbVh + off);
                ldsm_x4_t(vl4, sbVl + off);
                float* o0 = o[nn * 2 + 0];
                float* o1 = o[nn * 2 + 1];
                mma16816(o0, pah, &vh4[0]);
                mma16816(o1, pah, &vh4[2]);
                mma16816(o0, pah, &vl4[0]);
                mma16816(o1, pah, &vl4[2]);
                mma16816(o0, pal, &vh4[0]);
                mma16816(o1, pal, &vh4[2]);
            }
        }
        __syncthreads();
    }

    // Epilogue
    float inv0 = 1.0f / l0, inv1 = 1.0f / l1;
    int n0r = qt * 128 + wid * 16 + (lane >> 2);
#pragma unroll
    for (int f = 0; f < 8; f++) {
        int colc = h * Dq + f * 8 + 2 * (lane & 3);
        size_t i0 = ((size_t)(b * Nq + n0r)) * Cq + colc;
        size_t i1 = ((size_t)(b * Nq + n0r + 8)) * Cq + colc;
        uint32_t hi, lo;
        split2(o[f][0] * inv0, o[f][1] * inv0, hi, lo);
        *(uint32_t*)&g_aoh[i0] = hi; *(uint32_t*)&g_aol[i0] = lo;
        split2(o[f][2] * inv1, o[f][3] * inv1, hi, lo);
        *(uint32_t*)&g_aoh[i1] = hi; *(uint32_t*)&g_aol[i1] = lo;
    }
}

// ---------------------------------------------------------------------------
extern "C" void kernel_launch(void* const* d_in, const int* in_sizes, int n_in,
                              void* d_out, int out_size) {
    const float* query     = (const float*)d_in[0];
    const float* mask      = (const float*)d_in[1];
    const float* W_qkv     = (const float*)d_in[2];
    const float* magnitude = (const float*)d_in[3];
    const float* W_loraA   = (const float*)d_in[4];
    const float* W_loraB   = (const float*)d_in[5];
    const float* W_proj    = (const float*)d_in[6];
    float* out = (float*)d_out;

    cudaFuncSetAttribute(mma_gemm_kernel<0>,
        cudaFuncAttributeMaxDynamicSharedMemorySize, SMEM_GEMM);
    cudaFuncSetAttribute(mma_gemm_kernel<1>,
        cudaFuncAttributeMaxDynamicSharedMemorySize, SMEM_GEMM);
    cudaFuncSetAttribute(attn_mma_kernel,
        cudaFuncAttributeMaxDynamicSharedMemorySize, SMEM_ATTN);

    __nv_bfloat16 *gAh, *gAl, *gBh, *gBl, *gaoh, *gaol;
    cudaGetSymbolAddress((void**)&gAh,  g_Ah);
    cudaGetSymbolAddress((void**)&gAl,  g_Al);
    cudaGetSymbolAddress((void**)&gBh,  g_Bh);
    cudaGetSymbolAddress((void**)&gBl,  g_Bl);
    cudaGetSymbolAddress((void**)&gaoh, g_aoh);
    cudaGetSymbolAddress((void**)&gaol, g_aol);

    // Stage 1: conversions (LoRA folded into qkv weights algebraically)
    split_kernel<<<(Mq * Cq / 4) / 256, 256>>>(query, gAh, gAl);
    transpose_split_qkv_kernel<<<dim3(C3q / 32, Cq / 32), dim3(32, 8)>>>(
        W_qkv, W_loraA, W_loraB, magnitude, gBh, gBl);

    // Stage 2: qkv GEMM -> split-bf16 q/k/v
    mma_gemm_kernel<0><<<dim3(C3q / 128, Mq / 128), 256, SMEM_GEMM>>>(gAh, gAl, gBh, gBl, nullptr);

    // Stage 3: attention (mask + K/V cp.async pipelined)
    attn_mma_kernel<<<dim3(Hq, Nq / 128, Bq), 256, SMEM_ATTN>>>(mask);

    // Stage 4: proj GEMM
    transpose_split_kernel<<<dim3(Cq / 32, Cq / 32), dim3(32, 8)>>>(W_proj, gBh, gBl, Cq, Cq);
    mma_gemm_kernel<1><<<dim3(Cq / 128, Mq / 128), 256, SMEM_GEMM>>>(gaoh, gaol, gBh, gBl, out);
}